// round 9
// baseline (speedup 1.0000x reference)
#include <cuda_runtime.h>
#include <cuda_fp16.h>
typedef unsigned long long ull;
typedef unsigned int u32;
#define BB 16
#define NN 256
#define HH 768
#define PP 2048
#define RR 3
#define MROWS 4096
#define WSCALE 1024.0f
#define DSCALE 0.0009765625f

// fp16 hi/lo planes (mma chain)
__device__ __align__(16) __half g_WhtH[HH*PP], g_WhtL[HH*PP];
__device__ __align__(16) __half g_WttH[HH*PP], g_WttL[HH*PP];
__device__ __align__(16) __half g_WrtH[RR*PP*PP], g_WrtL[RR*PP*PP];
__device__ __align__(16) __half g_FH[MROWS*HH], g_FL[MROWS*HH];
__device__ __align__(16) __half g_T1H[RR*HH*PP], g_T1L[RR*HH*PP];
__device__ __align__(16) __half g_MtH[RR*HH*HH], g_MtL[RR*HH*HH];
__device__ __align__(16) __half g_GH[RR*MROWS*HH], g_GL[RR*MROWS*HH];
// fp32 scratch (fallback chain)
__device__ float g_T1f[RR*HH*PP];
__device__ float g_Mf [RR*HH*HH];
__device__ float g_Gf [RR*MROWS*HH];
// vec path
__device__ float g_w[RR*PP], g_zp[16*RR*PP], g_z[RR*PP];
__device__ float g_uvp[16*RR*HH], g_uv[2*RR*HH];
__device__ float g_fu[RR*MROWS], g_fv[RR*MROWS], g_s[RR];
// diagnostics
__device__ int g_mma_ok;
__device__ int g_conv_ok;

__device__ __forceinline__ void mma_f16(float* c,u32 a0,u32 a1,u32 a2,u32 a3,u32 b0,u32 b1){
    asm volatile("mma.sync.aligned.m16n8k16.row.col.f32.f16.f16.f32 "
        "{%0,%1,%2,%3}, {%4,%5,%6,%7}, {%8,%9}, {%0,%1,%2,%3};"
        :"+f"(c[0]),"+f"(c[1]),"+f"(c[2]),"+f"(c[3])
        :"r"(a0),"r"(a1),"r"(a2),"r"(a3),"r"(b0),"r"(b1));
}
__device__ __forceinline__ void split_h(float v,__half& h,__half& l){
    h=__float2half_rn(v); l=__float2half_rn(v-__half2float(h));
}
// f32x2 helpers
__device__ __forceinline__ ull ffma2(ull a,ull b,ull c){ ull d;
    asm("fma.rn.f32x2 %0, %1, %2, %3;":"=l"(d):"l"(a),"l"(b),"l"(c)); return d; }
__device__ __forceinline__ ull pack2(float x){ ull d;
    asm("mov.b64 %0, {%1, %1};":"=l"(d):"f"(x)); return d; }
__device__ __forceinline__ float2 unpk2(ull v){ float2 r;
    asm("mov.b64 {%0, %1}, %2;":"=f"(r.x),"=f"(r.y):"l"(v)); return r; }

// ---------------- mma staging (round-8 core) ----------------
#define LDROW 80
#define PLANE 10240
#define SMEM_DYN 40960

__device__ __forceinline__ void stage_compute(const char* stg,int wm,int wn,int lane,
                                              float acc[4][4][4])
{
    const int gid=lane>>2, tig=lane&3;
#pragma unroll
    for(int ks=0;ks<2;ks++){
        const u32 kb=(u32)ks*32+tig*4;
        u32 bh[4][2], bl[4][2];
#pragma unroll
        for(int nf=0;nf<4;nf++){
            const u32 rb=(u32)(wn*32+nf*8+gid)*LDROW+kb;
            bh[nf][0]=*(const u32*)(stg+2*PLANE+rb);
            bh[nf][1]=*(const u32*)(stg+2*PLANE+rb+16);
            bl[nf][0]=*(const u32*)(stg+3*PLANE+rb);
            bl[nf][1]=*(const u32*)(stg+3*PLANE+rb+16);
        }
#pragma unroll
        for(int mf=0;mf<4;mf++){
            const u32 r0=(u32)(wm*64+mf*16+gid)*LDROW+kb, r1=r0+8*LDROW;
            const u32 a0=*(const u32*)(stg+r0),       a1=*(const u32*)(stg+r1);
            const u32 a2=*(const u32*)(stg+r0+16),    a3=*(const u32*)(stg+r1+16);
            const u32 l0=*(const u32*)(stg+PLANE+r0), l1=*(const u32*)(stg+PLANE+r1);
            const u32 l2=*(const u32*)(stg+PLANE+r0+16), l3=*(const u32*)(stg+PLANE+r1+16);
#pragma unroll
            for(int nf=0;nf<4;nf++) mma_f16(acc[mf][nf],a0,a1,a2,a3,bh[nf][0],bh[nf][1]);
#pragma unroll
            for(int nf=0;nf<4;nf++) mma_f16(acc[mf][nf],l0,l1,l2,l3,bh[nf][0],bh[nf][1]);
#pragma unroll
            for(int nf=0;nf<4;nf++) mma_f16(acc[mf][nf],a0,a1,a2,a3,bl[nf][0],bl[nf][1]);
        }
    }
}

__device__ __forceinline__ void run_gemm(char* smem,
    const __half* __restrict__ Ah,const __half* __restrict__ Al,
    const __half* __restrict__ Bh,const __half* __restrict__ Bl,
    int K,int m0,int n0,float acc[4][4][4])
{
    const int tid=threadIdx.x, lane=tid&31, wid=tid>>5;
    const int wm=wid>>2, wn=wid&3;
    const int ns=K>>5;
    const int row=tid>>1, hf=tid&1;
    const u32 so=(u32)row*LDROW+hf*32;
    const __half* pa =Ah+(size_t)(m0+row)*K+hf*16;
    const __half* pal=Al+(size_t)(m0+row)*K+hf*16;
    const __half* pb =Bh+(size_t)(n0+row)*K+hf*16;
    const __half* pbl=Bl+(size_t)(n0+row)*K+hf*16;
    for(int s=0;s<ns;s++){
        const int kk=s*32;
        uint4 va[2],vb[2],vc[2],vd[2];
#pragma unroll
        for(int c=0;c<2;c++){ va[c]=*(const uint4*)(pa +kk+c*8);
                              vb[c]=*(const uint4*)(pal+kk+c*8);
                              vc[c]=*(const uint4*)(pb +kk+c*8);
                              vd[c]=*(const uint4*)(pbl+kk+c*8); }
        __syncthreads();
#pragma unroll
        for(int c=0;c<2;c++){
            *(uint4*)(smem+so+c*16)        =va[c];
            *(uint4*)(smem+PLANE+so+c*16)  =vb[c];
            *(uint4*)(smem+2*PLANE+so+c*16)=vc[c];
            *(uint4*)(smem+3*PLANE+so+c*16)=vd[c];
        }
        __syncthreads();
        stage_compute(smem,wm,wn,lane,acc);
    }
}

__device__ __forceinline__ void store_half_direct(const float acc[4][4][4],
    __half* CH,__half* CL,int ldo,int m0,int n0,float sc)
{
    const int lane=threadIdx.x&31, wid=threadIdx.x>>5;
    const int wm=wid>>2, wn=wid&3;
    const int gid=lane>>2, tig=lane&3;
#pragma unroll
    for(int mf=0;mf<4;mf++)
#pragma unroll
        for(int nf=0;nf<4;nf++){
            const int row=m0+wm*64+mf*16+gid;
            const int col=n0+wn*32+nf*8+tig*2;
            __half h0,l0,h1,l1;
            split_h(acc[mf][nf][0]*sc,h0,l0); split_h(acc[mf][nf][1]*sc,h1,l1);
            *(__half2*)(CH+(size_t)row*ldo+col)=__halves2half2(h0,h1);
            *(__half2*)(CL+(size_t)row*ldo+col)=__halves2half2(l0,l1);
            split_h(acc[mf][nf][2]*sc,h0,l0); split_h(acc[mf][nf][3]*sc,h1,l1);
            *(__half2*)(CH+(size_t)(row+8)*ldo+col)=__halves2half2(h0,h1);
            *(__half2*)(CL+(size_t)(row+8)*ldo+col)=__halves2half2(l0,l1);
        }
}

#define ACC_INIT float acc[4][4][4];                           \
    _Pragma("unroll") for(int i=0;i<4;i++)                     \
    _Pragma("unroll") for(int j=0;j<4;j++)                     \
    _Pragma("unroll") for(int q=0;q<4;q++) acc[i][j][q]=0.f;
#define ACC2_INIT ull acc2[4][8];                              \
    _Pragma("unroll") for(int i=0;i<4;i++)                     \
    _Pragma("unroll") for(int j=0;j<8;j++) acc2[i][j]=0ull;

// ---------------- FFMA2 fallback core: 128x128, BK=8 ----------------
template<bool AT,bool BT>
__device__ __forceinline__ void f32_core(char* smem,
    const float* __restrict__ A,int lda,const float* __restrict__ B,int ldb,
    int K,int m0,int n0, ull acc2[4][8])
{
    float (*As)[128]=(float(*)[128])smem;
    float (*Bs)[128]=(float(*)[128])(smem+4096);
    const int tid=threadIdx.x;
    const int kr=tid>>5, cc=(tid&31)*4;
    const int tr=tid>>1, tc=(tid&1)*4;
    const int tx=tid&15, ty=tid>>4;
    const int mm=ty*8, nn=tx*8;
    for(int k0=0;k0<K;k0+=8){
        float4 av = AT ? *(const float4*)(A+(size_t)(m0+tr)*lda+k0+tc)
                       : *(const float4*)(A+(size_t)(k0+kr)*lda+m0+cc);
        float4 bv = BT ? *(const float4*)(B+(size_t)(n0+tr)*ldb+k0+tc)
                       : *(const float4*)(B+(size_t)(k0+kr)*ldb+n0+cc);
        __syncthreads();
        if(AT){ As[tc+0][tr]=av.x; As[tc+1][tr]=av.y; As[tc+2][tr]=av.z; As[tc+3][tr]=av.w; }
        else  { *(float4*)&As[kr][cc]=av; }
        if(BT){ Bs[tc+0][tr]=bv.x; Bs[tc+1][tr]=bv.y; Bs[tc+2][tr]=bv.z; Bs[tc+3][tr]=bv.w; }
        else  { *(float4*)&Bs[kr][cc]=bv; }
        __syncthreads();
#pragma unroll
        for(int kk=0;kk<8;kk++){
            ull aa[4]={*(ull*)&As[kk][mm],*(ull*)&As[kk][mm+2],
                       *(ull*)&As[kk][mm+4],*(ull*)&As[kk][mm+6]};
            float4 b0=*(float4*)&Bs[kk][nn], b1=*(float4*)&Bs[kk][nn+4];
            ull bb[8]={pack2(b0.x),pack2(b0.y),pack2(b0.z),pack2(b0.w),
                       pack2(b1.x),pack2(b1.y),pack2(b1.z),pack2(b1.w)};
#pragma unroll
            for(int i=0;i<4;i++)
#pragma unroll
                for(int j=0;j<8;j++) acc2[i][j]=ffma2(aa[i],bb[j],acc2[i][j]);
        }
    }
}

__device__ __forceinline__ void store_f32_direct(const ull acc2[4][8],
    float* C,int ldc,int m0,int n0)
{
    const int tid=threadIdx.x, tx=tid&15, ty=tid>>4;
    const int mm=ty*8, nn=tx*8;
#pragma unroll
    for(int i=0;i<4;i++){
        float2 p[8];
#pragma unroll
        for(int j=0;j<8;j++) p[j]=unpk2(acc2[i][j]);
        float* r0=C+(size_t)(m0+mm+2*i)*ldc+n0+nn;
        float* r1=r0+ldc;
        *(float4*)r0    =make_float4(p[0].x,p[1].x,p[2].x,p[3].x);
        *(float4*)(r0+4)=make_float4(p[4].x,p[5].x,p[6].x,p[7].x);
        *(float4*)r1    =make_float4(p[0].y,p[1].y,p[2].y,p[3].y);
        *(float4*)(r1+4)=make_float4(p[4].y,p[5].y,p[6].y,p[7].y);
    }
}

// ---------------- self-tests ----------------
__global__ void mma_test_kernel(){
    __shared__ __align__(16) char stg[SMEM_DYN];
    const int lane=threadIdx.x;
    for(int idx=lane; idx<16*32; idx+=32){
        int m=idx>>5, k=idx&31;
        float av=(float)(((m*3+k)%5)-2);
        float al=0.25f*(float)(((m+k)%3)-1);
        *(__half*)(stg+m*LDROW+k*2)      =__float2half_rn(av);
        *(__half*)(stg+PLANE+m*LDROW+k*2)=__float2half_rn(al);
    }
    for(int idx=lane; idx<8*32; idx+=32){
        int n=idx>>5, k=idx&31;
        float bv=(float)(((n+k*7)%7)-3);
        float bl=0.25f*(float)(((n*5+k)%3)-1);
        *(__half*)(stg+2*PLANE+n*LDROW+k*2)=__float2half_rn(bv);
        *(__half*)(stg+3*PLANE+n*LDROW+k*2)=__float2half_rn(bl);
    }
    __syncwarp();
    const int gid=lane>>2, tig=lane&3;
    float acc[4]={0.f,0.f,0.f,0.f};
#pragma unroll
    for(int ks=0;ks<2;ks++){
        const u32 kb=(u32)ks*32+tig*4;
        const u32 rb=(u32)gid*LDROW+kb;
        u32 b0=*(u32*)(stg+2*PLANE+rb), b1=*(u32*)(stg+2*PLANE+rb+16);
        u32 c0=*(u32*)(stg+3*PLANE+rb), c1=*(u32*)(stg+3*PLANE+rb+16);
        const u32 r0=rb, r1=r0+8*LDROW;
        u32 a0=*(u32*)(stg+r0), a1=*(u32*)(stg+r1);
        u32 a2=*(u32*)(stg+r0+16), a3=*(u32*)(stg+r1+16);
        u32 l0=*(u32*)(stg+PLANE+r0), l1=*(u32*)(stg+PLANE+r1);
        u32 l2=*(u32*)(stg+PLANE+r0+16), l3=*(u32*)(stg+PLANE+r1+16);
        mma_f16(acc,a0,a1,a2,a3,b0,b1);
        mma_f16(acc,l0,l1,l2,l3,b0,b1);
        mma_f16(acc,a0,a1,a2,a3,c0,c1);
    }
    bool ok=true;
#pragma unroll
    for(int e=0;e<4;e++){
        const int m=gid+((e>=2)?8:0);
        const int n=tig*2+(e&1);
        float ref=0.f;
        for(int k=0;k<32;k++){
            float av=(float)(((m*3+k)%5)-2), al=0.25f*(float)(((m+k)%3)-1);
            float bv=(float)(((n+k*7)%7)-3), bl=0.25f*(float)(((n*5+k)%3)-1);
            ref += av*bv + al*bv + av*bl;
        }
        ok = ok && (fabsf(acc[e]-ref) < 1e-3f);
    }
    u32 vote=__ballot_sync(0xFFFFFFFFu, ok);
    if(lane==0) g_mma_ok = (vote==0xFFFFFFFFu) ? 1 : 0;
}

__global__ void conv_check_kernel(const float* __restrict__ hW,const float* __restrict__ tW,
                                  const float* __restrict__ rW,const float* __restrict__ F){
    const int tid=threadIdx.x;
    bool ok=true;
    for(int s=0;s<8;s++){
        const int p=(tid*97+s*251)%PP, h=(tid*31+s*77)%HH;
        __half e1=__float2half_rn(WSCALE*hW[(size_t)p*HH+h]);
        ok = ok && (__half_as_ushort(g_WhtH[(size_t)h*PP+p])==__half_as_ushort(e1));
        __half e2=__float2half_rn(WSCALE*tW[(size_t)p*HH+h]);
        ok = ok && (__half_as_ushort(g_WttH[(size_t)h*PP+p])==__half_as_ushort(e2));
        const int r=s%RR, q=(tid*53+s*131)%PP;
        __half e3=__float2half_rn(WSCALE*rW[(size_t)r*PP*PP+(size_t)p*PP+q]);
        ok = ok && (__half_as_ushort(g_WrtH[(size_t)r*PP*PP+(size_t)q*PP+p])==__half_as_ushort(e3));
        const int n=(tid*11+s*503)%MROWS;
        __half e4=__float2half_rn(F[(size_t)n*HH+h]);
        ok = ok && (__half_as_ushort(g_FH[(size_t)n*HH+h])==__half_as_ushort(e4));
    }
    __shared__ int sok;
    if(tid==0) sok=1;
    __syncthreads();
    if(!ok) atomicAnd(&sok,0);
    __syncthreads();
    if(tid==0) g_conv_ok=sok;
}

// ---------------- unified GEMM kernels ----------------
__global__ __launch_bounds__(256,1) void gemm1_kernel(const float* __restrict__ hW,
                                                      const float* __restrict__ rW){
    extern __shared__ char smem[];
    const int r=blockIdx.z, m0=blockIdx.y*128, n0=blockIdx.x*128;
    if(g_mma_ok && g_conv_ok){
        const size_t bo=(size_t)r*PP*PP;
        ACC_INIT;
        run_gemm(smem,g_WhtH,g_WhtL,g_WrtH+bo,g_WrtL+bo,PP,m0,n0,acc);
        const size_t co=(size_t)r*HH*PP;
        store_half_direct(acc,g_T1H+co,g_T1L+co,PP,m0,n0,DSCALE);
    }else{
        ACC2_INIT;
        f32_core<false,false>(smem,hW,HH,rW+(size_t)r*PP*PP,PP,PP,m0,n0,acc2);
        store_f32_direct(acc2,g_T1f+(size_t)r*HH*PP,PP,m0,n0);
    }
}
__global__ __launch_bounds__(256,1) void gemm2_kernel(const float* __restrict__ tW){
    extern __shared__ char smem[];
    const int r=blockIdx.z, m0=blockIdx.y*128, n0=blockIdx.x*128;
    if(g_mma_ok && g_conv_ok){
        const size_t bo=(size_t)r*HH*PP;
        ACC_INIT;
        run_gemm(smem,g_WttH,g_WttL,g_T1H+bo,g_T1L+bo,PP,m0,n0,acc);
        const size_t co=(size_t)r*HH*HH;
        store_half_direct(acc,g_MtH+co,g_MtL+co,HH,m0,n0,DSCALE);
    }else{
        ACC2_INIT;
        f32_core<true,false>(smem,g_T1f+(size_t)r*HH*PP,PP,tW,HH,PP,m0,n0,acc2);
        store_f32_direct(acc2,g_Mf+(size_t)r*HH*HH,HH,m0,n0);
    }
}
__global__ __launch_bounds__(256,1) void gemm3_kernel(const float* __restrict__ F){
    extern __shared__ char smem[];
    const int r=blockIdx.z, m0=blockIdx.y*128, n0=blockIdx.x*128;
    if(g_mma_ok && g_conv_ok){
        const size_t bo=(size_t)r*HH*HH;
        ACC_INIT;
        run_gemm(smem,g_FH,g_FL,g_MtH+bo,g_MtL+bo,HH,m0,n0,acc);
        const size_t co=(size_t)r*MROWS*HH;
        store_half_direct(acc,g_GH+co,g_GL+co,HH,m0,n0,1.0f);
    }else{
        ACC2_INIT;
        f32_core<true,false>(smem,F,HH,g_Mf+(size_t)r*HH*HH,HH,HH,m0,n0,acc2);
        store_f32_direct(acc2,g_Gf+(size_t)r*MROWS*HH,HH,m0,n0);
    }
}
__global__ __launch_bounds__(256,1) void gemm4_kernel(const float* __restrict__ F,
                                                      float* __restrict__ out){
    extern __shared__ char smem[];
    const int z=blockIdx.z, b=z/RR, r=z%RR;
    const int m0=blockIdx.y*128, n0=blockIdx.x*128;
    const float sv=g_s[r];
    const float* fu=g_fu+(size_t)r*MROWS+b*NN;
    const float* fv=g_fv+(size_t)r*MROWS+b*NN;
    if(g_mma_ok && g_conv_ok){
        const size_t ao=(size_t)r*MROWS*HH+(size_t)b*NN*HH;
        const size_t bo=(size_t)b*NN*HH;
        ACC_INIT;
        run_gemm(smem,g_GH+ao,g_GL+ao,g_FH+bo,g_FL+bo,HH,m0,n0,acc);
        const int lane=threadIdx.x&31, wid=threadIdx.x>>5;
        const int wm=wid>>2, wn=wid&3;
        const int gid=lane>>2, tig=lane&3;
#pragma unroll
        for(int mf=0;mf<4;mf++)
#pragma unroll
            for(int nf=0;nf<4;nf++){
                const int rn=m0+wm*64+mf*16+gid;
                const int cm=n0+wn*32+nf*8+tig*2;
                const float fv0=fv[cm]+sv, fv1=fv[cm+1]+sv;
                float* o0=out+(((size_t)b*NN+rn)*NN+cm)*RR+r;
                o0[0] =acc[mf][nf][0]*DSCALE+fu[rn]+fv0;
                o0[RR]=acc[mf][nf][1]*DSCALE+fu[rn]+fv1;
                float* o1=out+(((size_t)b*NN+rn+8)*NN+cm)*RR+r;
                o1[0] =acc[mf][nf][2]*DSCALE+fu[rn+8]+fv0;
                o1[RR]=acc[mf][nf][3]*DSCALE+fu[rn+8]+fv1;
            }
    }else{
        const size_t ao=(size_t)r*MROWS*HH+(size_t)b*NN*HH;
        const size_t bo=(size_t)b*NN*HH;
        ACC2_INIT;
        f32_core<true,true>(smem,g_Gf+ao,HH,F+bo,HH,HH,m0,n0,acc2);
        const int tid=threadIdx.x, tx=tid&15, ty=tid>>4;
        const int mm=ty*8, nn=tx*8;
#pragma unroll
        for(int i=0;i<4;i++){
            float2 p[8];
#pragma unroll
            for(int j=0;j<8;j++) p[j]=unpk2(acc2[i][j]);
            const int rn=m0+mm+2*i;
            const float fu0=fu[rn], fu1=fu[rn+1];
            float* o0=out+(((size_t)b*NN+rn)*NN+n0+nn)*RR+r;
            float* o1=o0+(size_t)NN*RR;
#pragma unroll
            for(int j=0;j<8;j++){
                const float fvj=fv[n0+nn+j]+sv;
                o0[(size_t)j*RR]=p[j].x+fu0+fvj;
                o1[(size_t)j*RR]=p[j].y+fu1+fvj;
            }
        }
    }
}

// ---------------- conversions ----------------
__global__ void conv_split_T(const float* __restrict__ src,__half* __restrict__ dH,
                             __half* __restrict__ dL,int rows,int cols,size_t zS,float sc){
    __shared__ float t[32][33];
    const float* s=src+(size_t)blockIdx.z*zS;
    __half* oH=dH+(size_t)blockIdx.z*zS;
    __half* oL=dL+(size_t)blockIdx.z*zS;
    const int tx=threadIdx.x&31, ty=threadIdx.x>>5;
    const int c=blockIdx.x*32+tx, rb=blockIdx.y*32;
#pragma unroll
    for(int i=0;i<4;i++) t[ty+i*8][tx]=s[(size_t)(rb+ty+i*8)*cols+c];
    __syncthreads();
    const int orow=blockIdx.x*32+ty, ocol=rb+tx;
#pragma unroll
    for(int i=0;i<4;i++){
        const float v=t[tx][ty+i*8]*sc;
        __half h,l; split_h(v,h,l);
        const size_t o=(size_t)(orow+i*8)*rows+ocol;
        oH[o]=h; oL[o]=l;
    }
}
__global__ void conv_split(const float4* __restrict__ src,__half* __restrict__ dH,
                           __half* __restrict__ dL){
    const int i=blockIdx.x*256+threadIdx.x;
    const float4 v=src[i];
    __half h0,l0,h1,l1,h2,l2,h3,l3;
    split_h(v.x,h0,l0); split_h(v.y,h1,l1); split_h(v.z,h2,l2); split_h(v.w,h3,l3);
    ((__half2*)dH)[i*2+0]=__halves2half2(h0,h1);
    ((__half2*)dH)[i*2+1]=__halves2half2(h2,h3);
    ((__half2*)dL)[i*2+0]=__halves2half2(l0,l1);
    ((__half2*)dL)[i*2+1]=__halves2half2(l2,l3);
}

// ---------------- vector/bias path (proven) ----------------
__global__ void vec_w_kernel(const float* __restrict__ bilW,const float* __restrict__ bt){
    const int r=blockIdx.y, warp=threadIdx.x>>5, lane=threadIdx.x&31;
    const int p=blockIdx.x*8+warp;
    const float* row=bilW+((size_t)r*PP+p)*PP;
    float a=0.f;
    for(int q=lane;q<PP;q+=32) a+=row[q]*__ldg(&bt[q]);
#pragma unroll
    for(int o=16;o;o>>=1) a+=__shfl_down_sync(0xFFFFFFFFu,a,o);
    if(lane==0) g_w[r*PP+p]=a;
}
__global__ void vec_z_part(const float* __restrict__ bilW,const float* __restrict__ bh){
    const int r=blockIdx.y, sp=blockIdx.z;
    const int q=blockIdx.x*256+threadIdx.x;
    const float* base=bilW+(size_t)r*PP*PP+(size_t)sp*128*PP+q;
    float a=0.f;
#pragma unroll 4
    for(int p=0;p<128;p++) a+=__ldg(&bh[sp*128+p])*base[(size_t)p*PP];
    g_zp[((size_t)sp*RR+r)*PP+q]=a;
}
__global__ void reduce_z(){
    const int o=blockIdx.x*256+threadIdx.x;
    float a=0.f;
#pragma unroll
    for(int sp=0;sp<16;sp++) a+=g_zp[(size_t)sp*RR*PP+o];
    g_z[o]=a;
}
__global__ void vec_s_kernel(const float* __restrict__ bh,const float* __restrict__ bilb){
    const int r=blockIdx.x;
    __shared__ float red[256];
    float a=0.f;
    for(int p=threadIdx.x;p<PP;p+=256) a+=bh[p]*g_w[r*PP+p];
    red[threadIdx.x]=a; __syncthreads();
    for(int o=128;o;o>>=1){
        if(threadIdx.x<o) red[threadIdx.x]+=red[threadIdx.x+o];
        __syncthreads();
    }
    if(threadIdx.x==0) g_s[r]=red[0]+bilb[r];
}
__global__ void vec_uv_part(const float* __restrict__ hW,const float* __restrict__ tW){
    const int sel=blockIdx.z>>3, sp=blockIdx.z&7;
    const int r=blockIdx.y;
    const int h=blockIdx.x*256+threadIdx.x;
    const float* Wm=sel?tW:hW;
    const float* vin=(sel?g_z:g_w)+(size_t)r*PP+sp*256;
    const float* base=Wm+(size_t)sp*256*HH+h;
    float a=0.f;
#pragma unroll 4
    for(int p=0;p<256;p++) a+=base[(size_t)p*HH]*__ldg(&vin[p]);
    g_uvp[((size_t)(sel*8+sp)*RR+r)*HH+h]=a;
}
__global__ void reduce_uv(){
    const int o=blockIdx.x*256+threadIdx.x;
    const int sel=o/(RR*HH), rem=o%(RR*HH);
    float a=0.f;
#pragma unroll
    for(int sp=0;sp<8;sp++) a+=g_uvp[((size_t)(sel*8+sp)*RR*HH)+rem];
    g_uv[o]=a;
}
__global__ void vec_fufv_kernel(const float* __restrict__ F){
    const int sel=blockIdx.z, r=blockIdx.y;
    const int warp=threadIdx.x>>5, lane=threadIdx.x&31;
    const int n=blockIdx.x*8+warp;
    const float* f=F+(size_t)n*HH;
    const float* vv=g_uv+((size_t)sel*RR+r)*HH;
    float a=0.f;
    for(int h=lane;h<HH;h+=32) a+=f[h]*__ldg(&vv[h]);
#pragma unroll
    for(int o=16;o;o>>=1) a+=__shfl_down_sync(0xFFFFFFFFu,a,o);
    if(lane==0) (sel?g_fv:g_fu)[r*MROWS+n]=a;
}

extern "C" void kernel_launch(void* const* d_in,const int* in_sizes,int n_in,
                              void* d_out,int out_size)
{
    const float* features=(const float*)d_in[0];
    const float* head_W  =(const float*)d_in[1];
    const float* head_b  =(const float*)d_in[2];
    const float* tail_W  =(const float*)d_in[3];
    const float* tail_b  =(const float*)d_in[4];
    const float* bil_W   =(const float*)d_in[5];
    const float* bil_b   =(const float*)d_in[6];
    float* out=(float*)d_out;

    dim3 blk(256);
    conv_split_T<<<dim3(HH/32,PP/32,1),blk>>>(head_W,g_WhtH,g_WhtL,PP,HH,0,WSCALE);
    conv_split_T<<<dim3(HH/32,PP/32,1),blk>>>(tail_W,g_WttH,g_WttL,PP,HH,0,WSCALE);
    conv_split_T<<<dim3(PP/32,PP/32,RR),blk>>>(bil_W,g_WrtH,g_WrtL,PP,PP,(size_t)PP*PP,WSCALE);
    conv_split<<<dim3(MROWS*HH/4/256),blk>>>((const float4*)features,g_FH,g_FL);

    vec_w_kernel<<<dim3(PP/8,RR),blk>>>(bil_W,tail_b);
    vec_z_part<<<dim3(PP/256,RR,16),blk>>>(bil_W,head_b);
    reduce_z<<<dim3(RR*PP/256),blk>>>();
    vec_s_kernel<<<dim3(RR),blk>>>(head_b,bil_b);
    vec_uv_part<<<dim3(HH/256,RR,16),blk>>>(head_W,tail_W);
    reduce_uv<<<dim3(2*RR*HH/256),blk>>>();
    vec_fufv_kernel<<<dim3(MROWS/8,RR,2),blk>>>(features);

    mma_test_kernel<<<1,32>>>();
    conv_check_kernel<<<1,256>>>(head_W,tail_W,bil_W,features);

    gemm1_kernel<<<dim3(PP/128,HH/128,RR),blk,SMEM_DYN>>>(head_W,bil_W);
    gemm2_kernel<<<dim3(HH/128,HH/128,RR),blk,SMEM_DYN>>>(tail_W);
    gemm3_kernel<<<dim3(HH/128,MROWS/128,RR),blk,SMEM_DYN>>>(features);
    gemm4_kernel<<<dim3(NN/128,NN/128,BB*RR),blk,SMEM_DYN>>>(features,out);
}

// round 10
// speedup vs baseline: 1.5394x; 1.5394x over previous
#include <cuda_runtime.h>

#define BB 16
#define NN 256
#define HH 768
#define PP 2048
#define RR 3
#define MROWS 4096

typedef unsigned long long ull;

// Scratch (__device__ globals; allocation forbidden)
__device__ float g_T1 [RR * HH * PP];       // Wh^T Wr          [3,768,2048]
__device__ float g_Mp [2 * RR * HH * HH];   // gemm2 split-K partials
__device__ float g_M  [RR * HH * HH];       // Wh^T Wr Wt       [3,768,768]
__device__ float g_G  [RR * MROWS * HH];    // F @ M_r          [3,4096,768]
__device__ float g_w  [RR * PP];
__device__ float g_zp [16 * RR * PP];
__device__ float g_z  [RR * PP];
__device__ float g_uvp[16 * RR * HH];
__device__ float g_uv [2 * RR * HH];
__device__ float g_fu [RR * MROWS];
__device__ float g_fv [RR * MROWS];
__device__ float g_s  [RR];

// ---------------------------------------------------------------------------
// Packed fp32x2 helpers
// ---------------------------------------------------------------------------
__device__ __forceinline__ ull ffma2(ull a, ull b, ull c) {
    ull d;
    asm("fma.rn.f32x2 %0, %1, %2, %3;" : "=l"(d) : "l"(a), "l"(b), "l"(c));
    return d;
}
__device__ __forceinline__ float2 unpk2(ull v) {
    float2 r;
    asm("mov.b64 {%0, %1}, %2;" : "=f"(r.x), "=f"(r.y) : "l"(v));
    return r;
}
union F4U { float4 f; ull u[2]; };
union U4U { uint4 v; ull u[2]; };

// ---------------------------------------------------------------------------
// SGEMM core: block tile 256(m) x 128(n), BK=8, 256 threads, 1 CTA/SM.
// Per-thread micro-tile 16x8: rows {ty*8..+7} u {128+ty*8..+7} (f32x2 pairs
// along m), cols {tx*4..+3} u {64+tx*4..+3}.
// B is stored PRE-DUPLICATED in smem (float2(b,b)) so the inner loop has no
// pack MOVs: 64 FFMA2 + 8 LDS.128 per k-step per thread.
//  AT=false: A stored [K, M];  AT=true: A stored [M, K].  BT analogous.
// ---------------------------------------------------------------------------
__device__ __forceinline__ void mm256(const float (*As)[256], const float2 (*Bs)[128],
                                      int ty, int tx, ull acc[8][8])
{
    const int ma0 = ty * 8, ma1 = 128 + ty * 8;
    const int na0 = tx * 4, na1 = 64 + tx * 4;
#pragma unroll
    for (int kk = 0; kk < 8; kk++) {
        F4U a0, a1, a2, a3;
        a0.f = *(const float4*)&As[kk][ma0];
        a1.f = *(const float4*)&As[kk][ma0 + 4];
        a2.f = *(const float4*)&As[kk][ma1];
        a3.f = *(const float4*)&As[kk][ma1 + 4];
        U4U b01, b23, b45, b67;
        b01.v = *(const uint4*)&Bs[kk][na0];
        b23.v = *(const uint4*)&Bs[kk][na0 + 2];
        b45.v = *(const uint4*)&Bs[kk][na1];
        b67.v = *(const uint4*)&Bs[kk][na1 + 2];
        ull aa[8] = {a0.u[0], a0.u[1], a1.u[0], a1.u[1],
                     a2.u[0], a2.u[1], a3.u[0], a3.u[1]};
        ull bb[8] = {b01.u[0], b01.u[1], b23.u[0], b23.u[1],
                     b45.u[0], b45.u[1], b67.u[0], b67.u[1]};
#pragma unroll
        for (int mi = 0; mi < 8; mi++)
#pragma unroll
            for (int j = 0; j < 8; j++)
                acc[mi][j] = ffma2(aa[mi], bb[j], acc[mi][j]);
    }
}

template<bool AT, bool BT>
__device__ __forceinline__ void gemm_core(const float* __restrict__ A, int lda,
                                          const float* __restrict__ B, int ldb,
                                          int K, int m0, int n0,
                                          int ty, int tx, ull acc[8][8])
{
    __shared__ float  As[2][8][256];
    __shared__ float2 Bs[2][8][128];
    const int tid = threadIdx.x;

    const int akr = tid >> 5, acol = (tid & 31) * 8;   // A direct: 32 thr x 8 floats
    const int bkr = tid >> 5, bcol = (tid & 31) * 4;   // B direct: 32 thr x 4 floats
    const int btr = tid >> 1, btc = (tid & 1) * 4;     // B transposed

    const float* Ap = AT ? (A + (size_t)(m0 + tid) * lda)
                         : (A + (size_t)akr * lda + m0 + acol);
    const float* Bp = BT ? (B + (size_t)(n0 + btr) * ldb + btc)
                         : (B + (size_t)bkr * ldb + n0 + bcol);

    float4 av0, av1, bv;
    // prologue: stage tile 0
    av0 = *(const float4*)(Ap); av1 = *(const float4*)(Ap + 4);
    bv  = *(const float4*)(Bp);
    if (AT) {
        As[0][0][tid] = av0.x; As[0][1][tid] = av0.y; As[0][2][tid] = av0.z; As[0][3][tid] = av0.w;
        As[0][4][tid] = av1.x; As[0][5][tid] = av1.y; As[0][6][tid] = av1.z; As[0][7][tid] = av1.w;
    } else {
        *(float4*)&As[0][akr][acol] = av0; *(float4*)&As[0][akr][acol + 4] = av1;
    }
    if (BT) {
        Bs[0][btc + 0][btr] = make_float2(bv.x, bv.x);
        Bs[0][btc + 1][btr] = make_float2(bv.y, bv.y);
        Bs[0][btc + 2][btr] = make_float2(bv.z, bv.z);
        Bs[0][btc + 3][btr] = make_float2(bv.w, bv.w);
    } else {
        float2* bd = &Bs[0][bkr][bcol];
        bd[0] = make_float2(bv.x, bv.x); bd[1] = make_float2(bv.y, bv.y);
        bd[2] = make_float2(bv.z, bv.z); bd[3] = make_float2(bv.w, bv.w);
    }
    __syncthreads();

    int buf = 0;
    for (int k0 = 8; k0 < K; k0 += 8) {
        if (AT) { av0 = *(const float4*)(Ap + k0); av1 = *(const float4*)(Ap + k0 + 4); }
        else    { av0 = *(const float4*)(Ap + (size_t)k0 * lda);
                  av1 = *(const float4*)(Ap + (size_t)k0 * lda + 4); }
        bv = BT ? *(const float4*)(Bp + k0) : *(const float4*)(Bp + (size_t)k0 * ldb);

        mm256(As[buf], Bs[buf], ty, tx, acc);

        const int nb = buf ^ 1;
        if (AT) {
            As[nb][0][tid] = av0.x; As[nb][1][tid] = av0.y; As[nb][2][tid] = av0.z; As[nb][3][tid] = av0.w;
            As[nb][4][tid] = av1.x; As[nb][5][tid] = av1.y; As[nb][6][tid] = av1.z; As[nb][7][tid] = av1.w;
        } else {
            *(float4*)&As[nb][akr][acol] = av0; *(float4*)&As[nb][akr][acol + 4] = av1;
        }
        if (BT) {
            Bs[nb][btc + 0][btr] = make_float2(bv.x, bv.x);
            Bs[nb][btc + 1][btr] = make_float2(bv.y, bv.y);
            Bs[nb][btc + 2][btr] = make_float2(bv.z, bv.z);
            Bs[nb][btc + 3][btr] = make_float2(bv.w, bv.w);
        } else {
            float2* bd = &Bs[nb][bkr][bcol];
            bd[0] = make_float2(bv.x, bv.x); bd[1] = make_float2(bv.y, bv.y);
            bd[2] = make_float2(bv.z, bv.z); bd[3] = make_float2(bv.w, bv.w);
        }
        __syncthreads();
        buf = nb;
    }
    mm256(As[buf], Bs[buf], ty, tx, acc);
}

#define MICRO_IDX                                   \
    const int tid = threadIdx.x;                    \
    const int tx = tid & 15, ty = tid >> 4;         \
    ull acc[8][8];                                  \
    _Pragma("unroll") for (int i = 0; i < 8; i++)   \
    _Pragma("unroll") for (int j = 0; j < 8; j++) acc[i][j] = 0ull;

__device__ __forceinline__ int mrow_of(int mi, int ty) {
    return (mi < 4) ? (ty * 8 + 2 * mi) : (128 + ty * 8 + 2 * (mi - 4));
}

__device__ __forceinline__ void store_plain(float* C, int ldc, int m0, int n0,
                                            int ty, int tx, const ull acc[8][8])
{
    const int na0 = n0 + tx * 4, na1 = n0 + 64 + tx * 4;
#pragma unroll
    for (int mi = 0; mi < 8; mi++) {
        const int row = m0 + mrow_of(mi, ty);
        float2 p[8];
#pragma unroll
        for (int j = 0; j < 8; j++) p[j] = unpk2(acc[mi][j]);
        float* r0 = C + (size_t)row * ldc;
        float* r1 = C + (size_t)(row + 1) * ldc;
        *(float4*)(r0 + na0) = make_float4(p[0].x, p[1].x, p[2].x, p[3].x);
        *(float4*)(r0 + na1) = make_float4(p[4].x, p[5].x, p[6].x, p[7].x);
        *(float4*)(r1 + na0) = make_float4(p[0].y, p[1].y, p[2].y, p[3].y);
        *(float4*)(r1 + na1) = make_float4(p[4].y, p[5].y, p[6].y, p[7].y);
    }
}

// ---------------------------------------------------------------------------
// gemm1: T1_r[h,q] = sum_p Wh[p,h] * Wr[r,p,q]   M=768 N=2048 K=2048
// ---------------------------------------------------------------------------
__global__ __launch_bounds__(256, 1) void gemm1_kernel(
    const float* __restrict__ hW, const float* __restrict__ bilW)
{
    const int r  = blockIdx.z;
    const int m0 = blockIdx.y * 256;
    const int n0 = blockIdx.x * 128;
    MICRO_IDX;
    gemm_core<false, false>(hW, HH, bilW + (size_t)r * PP * PP, PP,
                            PP, m0, n0, ty, tx, acc);
    store_plain(g_T1 + (size_t)r * HH * PP, PP, m0, n0, ty, tx, acc);
}

// ---------------------------------------------------------------------------
// gemm2 (split-K=2): Mp[kh][r][h,h2] = sum_{q half} T1_r[h,q] * Wt[q,h2]
// ---------------------------------------------------------------------------
__global__ __launch_bounds__(256, 1) void gemm2_kernel(const float* __restrict__ tW)
{
    const int z  = blockIdx.z;
    const int r  = z >> 1;
    const int kh = z & 1;
    const int m0 = blockIdx.y * 256;
    const int n0 = blockIdx.x * 128;
    MICRO_IDX;
    gemm_core<true, false>(g_T1 + (size_t)r * HH * PP + kh * 1024, PP,
                           tW + (size_t)kh * 1024 * HH, HH,
                           1024, m0, n0, ty, tx, acc);
    store_plain(g_Mp + ((size_t)kh * RR + r) * HH * HH, HH, m0, n0, ty, tx, acc);
}

__global__ void reduceM_kernel() {
    const int i = blockIdx.x * 256 + threadIdx.x;  // float4 index
    const float4 a = *((const float4*)g_Mp + i);
    const float4 b = *((const float4*)g_Mp + (size_t)RR * HH * HH / 4 + i);
    *((float4*)g_M + i) = make_float4(a.x + b.x, a.y + b.y, a.z + b.z, a.w + b.w);
}

// ---------------------------------------------------------------------------
// gemm3: G_r[n,h2] = sum_h F[n,h] * M_r[h,h2]    M=4096 N=768 K=768
// ---------------------------------------------------------------------------
__global__ __launch_bounds__(256, 1) void gemm3_kernel(const float* __restrict__ F)
{
    const int r  = blockIdx.z;
    const int m0 = blockIdx.y * 256;
    const int n0 = blockIdx.x * 128;
    MICRO_IDX;
    gemm_core<true, false>(F, HH, g_M + (size_t)r * HH * HH, HH,
                           HH, m0, n0, ty, tx, acc);
    store_plain(g_G + (size_t)r * MROWS * HH, HH, m0, n0, ty, tx, acc);
}

// ---------------------------------------------------------------------------
// gemm4: logits[b,n,m,r] = sum_h G_r[b*256+n,h]*F[b*256+m,h] + fu + fv + s
// ---------------------------------------------------------------------------
__global__ __launch_bounds__(256, 1) void gemm4_kernel(
    const float* __restrict__ F, float* __restrict__ out)
{
    const int z = blockIdx.z;
    const int b = z / RR;
    const int r = z % RR;
    const int n0 = blockIdx.x * 128;
    MICRO_IDX;
    gemm_core<true, true>(g_G + ((size_t)r * MROWS + (size_t)b * NN) * HH, HH,
                          F + (size_t)b * NN * HH, HH,
                          HH, 0, n0, ty, tx, acc);

    const float sv = g_s[r];
    const float* fu = g_fu + (size_t)r * MROWS + b * NN;
    const float* fv = g_fv + (size_t)r * MROWS + b * NN;

    const int na0 = n0 + tx * 4, na1 = n0 + 64 + tx * 4;
    float fvj[8];
#pragma unroll
    for (int j = 0; j < 4; j++) { fvj[j] = fv[na0 + j] + sv; fvj[j + 4] = fv[na1 + j] + sv; }

#pragma unroll
    for (int mi = 0; mi < 8; mi++) {
        const int n = mrow_of(mi, ty);
        const float fu0 = fu[n], fu1 = fu[n + 1];
        float2 p[8];
#pragma unroll
        for (int j = 0; j < 8; j++) p[j] = unpk2(acc[mi][j]);
        float* o0 = out + (((size_t)b * NN + n) * NN) * RR + r;
        float* o1 = o0 + (size_t)NN * RR;
#pragma unroll
        for (int j = 0; j < 4; j++) {
            o0[(size_t)(na0 + j) * RR] = p[j].x + fu0 + fvj[j];
            o0[(size_t)(na1 + j) * RR] = p[j + 4].x + fu0 + fvj[j + 4];
            o1[(size_t)(na0 + j) * RR] = p[j].y + fu1 + fvj[j];
            o1[(size_t)(na1 + j) * RR] = p[j + 4].y + fu1 + fvj[j + 4];
        }
    }
}

// ---------------------------------------------------------------------------
// Vector stage (deterministic partials + tree reduces) — proven
// ---------------------------------------------------------------------------
__global__ void vec_w_kernel(const float* __restrict__ bilW, const float* __restrict__ bt)
{
    const int r = blockIdx.y;
    const int warp = threadIdx.x >> 5, lane = threadIdx.x & 31;
    const int p = blockIdx.x * 8 + warp;
    const float* row = bilW + ((size_t)r * PP + p) * PP;
    float acc = 0.f;
    for (int q = lane; q < PP; q += 32) acc += row[q] * __ldg(&bt[q]);
#pragma unroll
    for (int o = 16; o; o >>= 1) acc += __shfl_down_sync(0xFFFFFFFFu, acc, o);
    if (lane == 0) g_w[r * PP + p] = acc;
}

__global__ void vec_z_part(const float* __restrict__ bilW, const float* __restrict__ bh)
{
    const int r = blockIdx.y, sp = blockIdx.z;
    const int q = blockIdx.x * 256 + threadIdx.x;
    const float* base = bilW + (size_t)r * PP * PP + (size_t)sp * 128 * PP + q;
    float acc = 0.f;
#pragma unroll 4
    for (int p = 0; p < 128; p++) acc += __ldg(&bh[sp * 128 + p]) * base[(size_t)p * PP];
    g_zp[((size_t)sp * RR + r) * PP + q] = acc;
}

__global__ void reduce_z() {
    const int o = blockIdx.x * 256 + threadIdx.x;
    float acc = 0.f;
#pragma unroll
    for (int sp = 0; sp < 16; sp++) acc += g_zp[(size_t)sp * RR * PP + o];
    g_z[o] = acc;
}

__global__ void vec_s_kernel(const float* __restrict__ bh, const float* __restrict__ bilb)
{
    const int r = blockIdx.x;
    __shared__ float red[256];
    float acc = 0.f;
    for (int p = threadIdx.x; p < PP; p += 256) acc += bh[p] * g_w[r * PP + p];
    red[threadIdx.x] = acc;
    __syncthreads();
    for (int o = 128; o; o >>= 1) {
        if (threadIdx.x < o) red[threadIdx.x] += red[threadIdx.x + o];
        __syncthreads();
    }
    if (threadIdx.x == 0) g_s[r] = red[0] + bilb[r];
}

__global__ void vec_uv_part(const float* __restrict__ hW, const float* __restrict__ tW)
{
    const int sel = blockIdx.z >> 3, sp = blockIdx.z & 7;
    const int r = blockIdx.y;
    const int h = blockIdx.x * 256 + threadIdx.x;
    const float* Wm  = sel ? tW : hW;
    const float* vin = (sel ? g_z : g_w) + (size_t)r * PP + sp * 256;
    const float* base = Wm + (size_t)sp * 256 * HH + h;
    float acc = 0.f;
#pragma unroll 4
    for (int p = 0; p < 256; p++) acc += base[(size_t)p * HH] * __ldg(&vin[p]);
    g_uvp[((size_t)(sel * 8 + sp) * RR + r) * HH + h] = acc;
}

__global__ void reduce_uv() {
    const int o = blockIdx.x * 256 + threadIdx.x;
    const int sel = o / (RR * HH);
    const int rem = o % (RR * HH);
    float acc = 0.f;
#pragma unroll
    for (int sp = 0; sp < 8; sp++) acc += g_uvp[((size_t)(sel * 8 + sp) * RR * HH) + rem];
    g_uv[o] = acc;
}

__global__ void vec_fufv_kernel(const float* __restrict__ F)
{
    const int sel = blockIdx.z;
    const int r = blockIdx.y;
    const int warp = threadIdx.x >> 5, lane = threadIdx.x & 31;
    const int n = blockIdx.x * 8 + warp;
    const float* f  = F + (size_t)n * HH;
    const float* vv = g_uv + ((size_t)sel * RR + r) * HH;
    float acc = 0.f;
    for (int h = lane; h < HH; h += 32) acc += f[h] * __ldg(&vv[h]);
#pragma unroll
    for (int o = 16; o; o >>= 1) acc += __shfl_down_sync(0xFFFFFFFFu, acc, o);
    if (lane == 0) (sel ? g_fv : g_fu)[r * MROWS + n] = acc;
}

// ---------------------------------------------------------------------------
// Launch
// ---------------------------------------------------------------------------
extern "C" void kernel_launch(void* const* d_in, const int* in_sizes, int n_in,
                              void* d_out, int out_size)
{
    const float* features = (const float*)d_in[0];
    const float* head_W   = (const float*)d_in[1];
    const float* head_b   = (const float*)d_in[2];
    const float* tail_W   = (const float*)d_in[3];
    const float* tail_b   = (const float*)d_in[4];
    const float* bil_W    = (const float*)d_in[5];
    const float* bil_b    = (const float*)d_in[6];
    float* out = (float*)d_out;

    dim3 blk(256);

    // vector/bias path
    vec_w_kernel  <<<dim3(PP / 8, RR), blk>>>(bil_W, tail_b);
    vec_z_part    <<<dim3(PP / 256, RR, 16), blk>>>(bil_W, head_b);
    reduce_z      <<<dim3(RR * PP / 256), blk>>>();
    vec_s_kernel  <<<dim3(RR), blk>>>(head_b, bil_b);
    vec_uv_part   <<<dim3(HH / 256, RR, 16), blk>>>(head_W, tail_W);
    reduce_uv     <<<dim3(2 * RR * HH / 256), blk>>>();
    vec_fufv_kernel<<<dim3(MROWS / 8, RR, 2), blk>>>(features);

    // factored GEMM chain (FFMA2, pre-duplicated B)
    gemm1_kernel  <<<dim3(PP / 128, HH / 256, RR), blk>>>(head_W, bil_W);
    gemm2_kernel  <<<dim3(HH / 128, HH / 256, RR * 2), blk>>>(tail_W);
    reduceM_kernel<<<dim3(RR * HH * HH / 4 / 256), blk>>>();
    gemm3_kernel  <<<dim3(HH / 128, MROWS / 256, RR), blk>>>(features);
    gemm4_kernel  <<<dim3(NN / 128, NN / 256, BB * RR), blk>>>(features, out);
}

// round 11
// speedup vs baseline: 1.7112x; 1.1117x over previous
#include <cuda_runtime.h>

#define BB 16
#define NN 256
#define HH 768
#define PP 2048
#define RR 3
#define MROWS 4096

typedef unsigned long long ull;

// Scratch (__device__ globals; allocation forbidden)
__device__ float g_T1 [RR * HH * PP];       // Wh^T Wr          [3,768,2048]
__device__ float g_Mp [2 * RR * HH * HH];   // gemm2 split-K partials
__device__ float g_M  [RR * HH * HH];       // Wh^T Wr Wt       [3,768,768]
__device__ float g_G  [RR * MROWS * HH];    // F @ M_r          [3,4096,768]
__device__ float g_w  [RR * PP];
__device__ float g_zp [16 * RR * PP];
__device__ float g_z  [RR * PP];
__device__ float g_uvp[16 * RR * HH];
__device__ float g_uv [2 * RR * HH];
__device__ float g_fu [RR * MROWS];
__device__ float g_fv [RR * MROWS];
__device__ float g_s  [RR];

// ---------------------------------------------------------------------------
// Packed fp32x2 helpers
// ---------------------------------------------------------------------------
__device__ __forceinline__ ull ffma2(ull a, ull b, ull c) {
    ull d;
    asm("fma.rn.f32x2 %0, %1, %2, %3;" : "=l"(d) : "l"(a), "l"(b), "l"(c));
    return d;
}
__device__ __forceinline__ float2 unpk2(ull v) {
    float2 r;
    asm("mov.b64 {%0, %1}, %2;" : "=f"(r.x), "=f"(r.y) : "l"(v));
    return r;
}
union F4U { float4 f; ull u[2]; };
union U4U { uint4 v; ull u[2]; };

// ---------------------------------------------------------------------------
// SGEMM core: block tile 256(m) x 128(n), BK=8, 256 threads, 1 CTA/SM.
// Per-thread micro-tile 16x8:
//   rows: {ty*8 + 2i} and {128 + ty*8 + 2i}, i=0..3, packed f32x2 along m.
//   cols (STRIDED): {32j + 2tx, 32j + 2tx + 1}, j=0..3.
// B stored pre-duplicated in smem (float2(b,b)); each uint4 B-fragment load is
// at byte (32j+2tx)*8 -> 16B lane stride -> conflict-free, covers 2 pairs.
// Inner loop: 64 FFMA2 + 4 A LDS.128 + 4 B LDS.128, no pack MOVs.
//  AT=false: A stored [K, M];  AT=true: A stored [M, K].  BT analogous.
// ---------------------------------------------------------------------------
__device__ __forceinline__ void mm256(const float (*As)[256], const float2 (*Bs)[128],
                                      int ty, int tx, ull acc[8][8])
{
    const int ma0 = ty * 8, ma1 = 128 + ty * 8;
    const int nb = tx * 2;
#pragma unroll
    for (int kk = 0; kk < 8; kk++) {
        F4U a0, a1, a2, a3;
        a0.f = *(const float4*)&As[kk][ma0];
        a1.f = *(const float4*)&As[kk][ma0 + 4];
        a2.f = *(const float4*)&As[kk][ma1];
        a3.f = *(const float4*)&As[kk][ma1 + 4];
        U4U b0, b1, b2, b3;
        b0.v = *(const uint4*)&Bs[kk][nb];
        b1.v = *(const uint4*)&Bs[kk][32 + nb];
        b2.v = *(const uint4*)&Bs[kk][64 + nb];
        b3.v = *(const uint4*)&Bs[kk][96 + nb];
        ull aa[8] = {a0.u[0], a0.u[1], a1.u[0], a1.u[1],
                     a2.u[0], a2.u[1], a3.u[0], a3.u[1]};
        ull bb[8] = {b0.u[0], b0.u[1], b1.u[0], b1.u[1],
                     b2.u[0], b2.u[1], b3.u[0], b3.u[1]};
#pragma unroll
        for (int mi = 0; mi < 8; mi++)
#pragma unroll
            for (int j = 0; j < 8; j++)
                acc[mi][j] = ffma2(aa[mi], bb[j], acc[mi][j]);
    }
}

template<bool AT, bool BT>
__device__ __forceinline__ void gemm_core(const float* __restrict__ A, int lda,
                                          const float* __restrict__ B, int ldb,
                                          int K, int m0, int n0,
                                          int ty, int tx, ull acc[8][8])
{
    __shared__ float  As[2][8][256];
    __shared__ float2 Bs[2][8][128];
    const int tid = threadIdx.x;

    const int akr = tid >> 5, acol = (tid & 31) * 8;   // A direct: 32 thr x 8 floats
    const int bkr = tid >> 5, bcol = (tid & 31) * 4;   // B direct: 32 thr x 4 floats
    const int btr = tid >> 1, btc = (tid & 1) * 4;     // B transposed

    const float* Ap = AT ? (A + (size_t)(m0 + tid) * lda)
                         : (A + (size_t)akr * lda + m0 + acol);
    const float* Bp = BT ? (B + (size_t)(n0 + btr) * ldb + btc)
                         : (B + (size_t)bkr * ldb + n0 + bcol);

    float4 av0, av1, bv;
    // prologue: stage tile 0
    av0 = *(const float4*)(Ap); av1 = *(const float4*)(Ap + 4);
    bv  = *(const float4*)(Bp);
    if (AT) {
        As[0][0][tid] = av0.x; As[0][1][tid] = av0.y; As[0][2][tid] = av0.z; As[0][3][tid] = av0.w;
        As[0][4][tid] = av1.x; As[0][5][tid] = av1.y; As[0][6][tid] = av1.z; As[0][7][tid] = av1.w;
    } else {
        *(float4*)&As[0][akr][acol] = av0; *(float4*)&As[0][akr][acol + 4] = av1;
    }
    if (BT) {
        Bs[0][btc + 0][btr] = make_float2(bv.x, bv.x);
        Bs[0][btc + 1][btr] = make_float2(bv.y, bv.y);
        Bs[0][btc + 2][btr] = make_float2(bv.z, bv.z);
        Bs[0][btc + 3][btr] = make_float2(bv.w, bv.w);
    } else {
        float2* bd = &Bs[0][bkr][bcol];
        bd[0] = make_float2(bv.x, bv.x); bd[1] = make_float2(bv.y, bv.y);
        bd[2] = make_float2(bv.z, bv.z); bd[3] = make_float2(bv.w, bv.w);
    }
    __syncthreads();

    int buf = 0;
    for (int k0 = 8; k0 < K; k0 += 8) {
        if (AT) { av0 = *(const float4*)(Ap + k0); av1 = *(const float4*)(Ap + k0 + 4); }
        else    { av0 = *(const float4*)(Ap + (size_t)k0 * lda);
                  av1 = *(const float4*)(Ap + (size_t)k0 * lda + 4); }
        bv = BT ? *(const float4*)(Bp + k0) : *(const float4*)(Bp + (size_t)k0 * ldb);

        mm256(As[buf], Bs[buf], ty, tx, acc);

        const int nb2 = buf ^ 1;
        if (AT) {
            As[nb2][0][tid] = av0.x; As[nb2][1][tid] = av0.y; As[nb2][2][tid] = av0.z; As[nb2][3][tid] = av0.w;
            As[nb2][4][tid] = av1.x; As[nb2][5][tid] = av1.y; As[nb2][6][tid] = av1.z; As[nb2][7][tid] = av1.w;
        } else {
            *(float4*)&As[nb2][akr][acol] = av0; *(float4*)&As[nb2][akr][acol + 4] = av1;
        }
        if (BT) {
            Bs[nb2][btc + 0][btr] = make_float2(bv.x, bv.x);
            Bs[nb2][btc + 1][btr] = make_float2(bv.y, bv.y);
            Bs[nb2][btc + 2][btr] = make_float2(bv.z, bv.z);
            Bs[nb2][btc + 3][btr] = make_float2(bv.w, bv.w);
        } else {
            float2* bd = &Bs[nb2][bkr][bcol];
            bd[0] = make_float2(bv.x, bv.x); bd[1] = make_float2(bv.y, bv.y);
            bd[2] = make_float2(bv.z, bv.z); bd[3] = make_float2(bv.w, bv.w);
        }
        __syncthreads();
        buf = nb2;
    }
    mm256(As[buf], Bs[buf], ty, tx, acc);
}

#define MICRO_IDX                                   \
    const int tid = threadIdx.x;                    \
    const int tx = tid & 15, ty = tid >> 4;         \
    ull acc[8][8];                                  \
    _Pragma("unroll") for (int i = 0; i < 8; i++)   \
    _Pragma("unroll") for (int j = 0; j < 8; j++) acc[i][j] = 0ull;

__device__ __forceinline__ int mrow_of(int mi, int ty) {
    return (mi < 4) ? (ty * 8 + 2 * mi) : (128 + ty * 8 + 2 * (mi - 4));
}

// Epilogue for strided-N mapping: acc[mi][2j+e] -> col n0 + 32j + 2tx + e.
__device__ __forceinline__ void store_plain(float* C, int ldc, int m0, int n0,
                                            int ty, int tx, const ull acc[8][8])
{
#pragma unroll
    for (int mi = 0; mi < 8; mi++) {
        const int row = m0 + mrow_of(mi, ty);
        float2 p[8];
#pragma unroll
        for (int j = 0; j < 8; j++) p[j] = unpk2(acc[mi][j]);
        float* r0 = C + (size_t)row * ldc + n0 + tx * 2;
        float* r1 = r0 + ldc;
#pragma unroll
        for (int jj = 0; jj < 4; jj++) {
            *(float2*)(r0 + jj * 32) = make_float2(p[2*jj].x, p[2*jj+1].x);
            *(float2*)(r1 + jj * 32) = make_float2(p[2*jj].y, p[2*jj+1].y);
        }
    }
}

// ---------------------------------------------------------------------------
// gemm1: T1_r[h,q] = sum_p Wh[p,h] * Wr[r,p,q]   M=768 N=2048 K=2048
// ---------------------------------------------------------------------------
__global__ __launch_bounds__(256, 1) void gemm1_kernel(
    const float* __restrict__ hW, const float* __restrict__ bilW)
{
    const int r  = blockIdx.z;
    const int m0 = blockIdx.y * 256;
    const int n0 = blockIdx.x * 128;
    MICRO_IDX;
    gemm_core<false, false>(hW, HH, bilW + (size_t)r * PP * PP, PP,
                            PP, m0, n0, ty, tx, acc);
    store_plain(g_T1 + (size_t)r * HH * PP, PP, m0, n0, ty, tx, acc);
}

// ---------------------------------------------------------------------------
// gemm2 (split-K=2): Mp[kh][r][h,h2] = sum_{q half} T1_r[h,q] * Wt[q,h2]
// ---------------------------------------------------------------------------
__global__ __launch_bounds__(256, 1) void gemm2_kernel(const float* __restrict__ tW)
{
    const int z  = blockIdx.z;
    const int r  = z >> 1;
    const int kh = z & 1;
    const int m0 = blockIdx.y * 256;
    const int n0 = blockIdx.x * 128;
    MICRO_IDX;
    gemm_core<true, false>(g_T1 + (size_t)r * HH * PP + kh * 1024, PP,
                           tW + (size_t)kh * 1024 * HH, HH,
                           1024, m0, n0, ty, tx, acc);
    store_plain(g_Mp + ((size_t)kh * RR + r) * HH * HH, HH, m0, n0, ty, tx, acc);
}

__global__ void reduceM_kernel() {
    const int i = blockIdx.x * 256 + threadIdx.x;  // float4 index
    const float4 a = *((const float4*)g_Mp + i);
    const float4 b = *((const float4*)g_Mp + (size_t)RR * HH * HH / 4 + i);
    *((float4*)g_M + i) = make_float4(a.x + b.x, a.y + b.y, a.z + b.z, a.w + b.w);
}

// ---------------------------------------------------------------------------
// gemm3: G_r[n,h2] = sum_h F[n,h] * M_r[h,h2]    M=4096 N=768 K=768
// ---------------------------------------------------------------------------
__global__ __launch_bounds__(256, 1) void gemm3_kernel(const float* __restrict__ F)
{
    const int r  = blockIdx.z;
    const int m0 = blockIdx.y * 256;
    const int n0 = blockIdx.x * 128;
    MICRO_IDX;
    gemm_core<true, false>(F, HH, g_M + (size_t)r * HH * HH, HH,
                           HH, m0, n0, ty, tx, acc);
    store_plain(g_G + (size_t)r * MROWS * HH, HH, m0, n0, ty, tx, acc);
}

// ---------------------------------------------------------------------------
// gemm4: logits[b,n,m,r] = sum_h G_r[b*256+n,h]*F[b*256+m,h] + fu + fv + s
// ---------------------------------------------------------------------------
__global__ __launch_bounds__(256, 1) void gemm4_kernel(
    const float* __restrict__ F, float* __restrict__ out)
{
    const int z = blockIdx.z;
    const int b = z / RR;
    const int r = z % RR;
    const int n0 = blockIdx.x * 128;
    MICRO_IDX;
    gemm_core<true, true>(g_G + ((size_t)r * MROWS + (size_t)b * NN) * HH, HH,
                          F + (size_t)b * NN * HH, HH,
                          HH, 0, n0, ty, tx, acc);

    const float sv = g_s[r];
    const float* fu = g_fu + (size_t)r * MROWS + b * NN;
    const float* fv = g_fv + (size_t)r * MROWS + b * NN;

    const int ncol = n0 + tx * 2;
    float fvj[8];
#pragma unroll
    for (int jj = 0; jj < 4; jj++) {
        fvj[2*jj]   = fv[ncol + 32*jj]     + sv;
        fvj[2*jj+1] = fv[ncol + 32*jj + 1] + sv;
    }

#pragma unroll
    for (int mi = 0; mi < 8; mi++) {
        const int n = mrow_of(mi, ty);
        const float fu0 = fu[n], fu1 = fu[n + 1];
        float2 p[8];
#pragma unroll
        for (int j = 0; j < 8; j++) p[j] = unpk2(acc[mi][j]);
        float* o0 = out + (((size_t)b * NN + n) * NN) * RR + r;
        float* o1 = o0 + (size_t)NN * RR;
#pragma unroll
        for (int jj = 0; jj < 4; jj++) {
#pragma unroll
            for (int e = 0; e < 2; e++) {
                const int cm = ncol + 32*jj + e;
                o0[(size_t)cm * RR] = p[2*jj+e].x + fu0 + fvj[2*jj+e];
                o1[(size_t)cm * RR] = p[2*jj+e].y + fu1 + fvj[2*jj+e];
            }
        }
    }
}

// ---------------------------------------------------------------------------
// Vector stage (deterministic partials + tree reduces) — proven
// ---------------------------------------------------------------------------
__global__ void vec_w_kernel(const float* __restrict__ bilW, const float* __restrict__ bt)
{
    const int r = blockIdx.y;
    const int warp = threadIdx.x >> 5, lane = threadIdx.x & 31;
    const int p = blockIdx.x * 8 + warp;
    const float* row = bilW + ((size_t)r * PP + p) * PP;
    float acc = 0.f;
    for (int q = lane; q < PP; q += 32) acc += row[q] * __ldg(&bt[q]);
#pragma unroll
    for (int o = 16; o; o >>= 1) acc += __shfl_down_sync(0xFFFFFFFFu, acc, o);
    if (lane == 0) g_w[r * PP + p] = acc;
}

__global__ void vec_z_part(const float* __restrict__ bilW, const float* __restrict__ bh)
{
    const int r = blockIdx.y, sp = blockIdx.z;
    const int q = blockIdx.x * 256 + threadIdx.x;
    const float* base = bilW + (size_t)r * PP * PP + (size_t)sp * 128 * PP + q;
    float acc = 0.f;
#pragma unroll 4
    for (int p = 0; p < 128; p++) acc += __ldg(&bh[sp * 128 + p]) * base[(size_t)p * PP];
    g_zp[((size_t)sp * RR + r) * PP + q] = acc;
}

__global__ void reduce_z() {
    const int o = blockIdx.x * 256 + threadIdx.x;
    float acc = 0.f;
#pragma unroll
    for (int sp = 0; sp < 16; sp++) acc += g_zp[(size_t)sp * RR * PP + o];
    g_z[o] = acc;
}

__global__ void vec_s_kernel(const float* __restrict__ bh, const float* __restrict__ bilb)
{
    const int r = blockIdx.x;
    __shared__ float red[256];
    float acc = 0.f;
    for (int p = threadIdx.x; p < PP; p += 256) acc += bh[p] * g_w[r * PP + p];
    red[threadIdx.x] = acc;
    __syncthreads();
    for (int o = 128; o; o >>= 1) {
        if (threadIdx.x < o) red[threadIdx.x] += red[threadIdx.x + o];
        __syncthreads();
    }
    if (threadIdx.x == 0) g_s[r] = red[0] + bilb[r];
}

__global__ void vec_uv_part(const float* __restrict__ hW, const float* __restrict__ tW)
{
    const int sel = blockIdx.z >> 3, sp = blockIdx.z & 7;
    const int r = blockIdx.y;
    const int h = blockIdx.x * 256 + threadIdx.x;
    const float* Wm  = sel ? tW : hW;
    const float* vin = (sel ? g_z : g_w) + (size_t)r * PP + sp * 256;
    const float* base = Wm + (size_t)sp * 256 * HH + h;
    float acc = 0.f;
#pragma unroll 4
    for (int p = 0; p < 256; p++) acc += base[(size_t)p * HH] * __ldg(&vin[p]);
    g_uvp[((size_t)(sel * 8 + sp) * RR + r) * HH + h] = acc;
}

__global__ void reduce_uv() {
    const int o = blockIdx.x * 256 + threadIdx.x;
    const int sel = o / (RR * HH);
    const int rem = o % (RR * HH);
    float acc = 0.f;
#pragma unroll
    for (int sp = 0; sp < 8; sp++) acc += g_uvp[((size_t)(sel * 8 + sp) * RR * HH) + rem];
    g_uv[o] = acc;
}

__global__ void vec_fufv_kernel(const float* __restrict__ F)
{
    const int sel = blockIdx.z;
    const int r = blockIdx.y;
    const int warp = threadIdx.x >> 5, lane = threadIdx.x & 31;
    const int n = blockIdx.x * 8 + warp;
    const float* f  = F + (size_t)n * HH;
    const float* vv = g_uv + ((size_t)sel * RR + r) * HH;
    float acc = 0.f;
    for (int h = lane; h < HH; h += 32) acc += f[h] * __ldg(&vv[h]);
#pragma unroll
    for (int o = 16; o; o >>= 1) acc += __shfl_down_sync(0xFFFFFFFFu, acc, o);
    if (lane == 0) (sel ? g_fv : g_fu)[r * MROWS + n] = acc;
}

// ---------------------------------------------------------------------------
// Launch
// ---------------------------------------------------------------------------
extern "C" void kernel_launch(void* const* d_in, const int* in_sizes, int n_in,
                              void* d_out, int out_size)
{
    const float* features = (const float*)d_in[0];
    const float* head_W   = (const float*)d_in[1];
    const float* head_b   = (const float*)d_in[2];
    const float* tail_W   = (const float*)d_in[3];
    const float* tail_b   = (const float*)d_in[4];
    const float* bil_W    = (const float*)d_in[5];
    const float* bil_b    = (const float*)d_in[6];
    float* out = (float*)d_out;

    dim3 blk(256);

    // vector/bias path
    vec_w_kernel  <<<dim3(PP / 8, RR), blk>>>(bil_W, tail_b);
    vec_z_part    <<<dim3(PP / 256, RR, 16), blk>>>(bil_W, head_b);
    reduce_z      <<<dim3(RR * PP / 256), blk>>>();
    vec_s_kernel  <<<dim3(RR), blk>>>(head_b, bil_b);
    vec_uv_part   <<<dim3(HH / 256, RR, 16), blk>>>(head_W, tail_W);
    reduce_uv     <<<dim3(2 * RR * HH / 256), blk>>>();
    vec_fufv_kernel<<<dim3(MROWS / 8, RR, 2), blk>>>(features);

    // factored GEMM chain (FFMA2, pre-duplicated B, strided-N micro-tile)
    gemm1_kernel  <<<dim3(PP / 128, HH / 256, RR), blk>>>(head_W, bil_W);
    gemm2_kernel  <<<dim3(HH / 128, HH / 256, RR * 2), blk>>>(tail_W);
    reduceM_kernel<<<dim3(RR * HH * HH / 4 / 256), blk>>>();
    gemm3_kernel  <<<dim3(HH / 128, MROWS / 256, RR), blk>>>(features);
    gemm4_kernel  <<<dim3(NN / 128, NN / 256, BB * RR), blk>>>(features, out);
}

// round 12
// speedup vs baseline: 2.0715x; 1.2105x over previous
#include <cuda_runtime.h>

#define BB 16
#define NN 256
#define HH 768
#define PP 2048
#define RR 3
#define MROWS 4096

typedef unsigned long long ull;

// Scratch (__device__ globals; allocation forbidden)
__device__ float g_T1 [RR * HH * PP];       // Wh^T Wr          [3,768,2048]
__device__ float g_Mp [2 * RR * HH * HH];   // gemm2 split-K partials
__device__ float g_G  [RR * MROWS * HH];    // F @ M_r          [3,4096,768]
__device__ float g_w  [RR * PP];
__device__ float g_zp [16 * RR * PP];
__device__ float g_z  [RR * PP];
__device__ float g_uvp[16 * RR * HH];
__device__ float g_uv [2 * RR * HH];
__device__ float g_fu [RR * MROWS];
__device__ float g_fv [RR * MROWS];
__device__ float g_s  [RR];

// ---------------------------------------------------------------------------
// Packed fp32x2 helpers
// ---------------------------------------------------------------------------
__device__ __forceinline__ ull ffma2(ull a, ull b, ull c) {
    ull d;
    asm("fma.rn.f32x2 %0, %1, %2, %3;" : "=l"(d) : "l"(a), "l"(b), "l"(c));
    return d;
}
__device__ __forceinline__ ull pack2(float x) {
    ull d;
    asm("mov.b64 %0, {%1, %1};" : "=l"(d) : "f"(x));
    return d;
}
__device__ __forceinline__ float2 unpk2(ull v) {
    float2 r;
    asm("mov.b64 {%0, %1}, %2;" : "=f"(r.x), "=f"(r.y) : "l"(v));
    return r;
}
union F4U { float4 f; ull u[2]; };

// ---------------------------------------------------------------------------
// SGEMM core (round-3 proven inner loop): block tile 256(m) x 128(n),
// BK=16 (halved sync frequency vs round 3), 256 threads, 1 CTA/SM.
// Per-thread micro-tile 16x8: rows {ty*8..+7} u {128+ty*8..+7} packed f32x2,
// cols {tx*4..+3} u {64+tx*4..+3}.
//  AT=false: A stored [K, M];  AT=true: A stored [M, K].  BT analogous.
//  SUMB: B staged as elementwise sum of B and B2 (folds reduceM into gemm3).
// ---------------------------------------------------------------------------
__device__ __forceinline__ void mm256(const float (*As)[256], const float (*Bs)[128],
                                      int ty, int tx, ull acc[8][8])
{
    const int ma0 = ty * 8, ma1 = 128 + ty * 8;
    const int na0 = tx * 4, na1 = 64 + tx * 4;
#pragma unroll
    for (int kk = 0; kk < 16; kk++) {
        F4U a0, a1, a2, a3;
        a0.f = *(const float4*)&As[kk][ma0];
        a1.f = *(const float4*)&As[kk][ma0 + 4];
        a2.f = *(const float4*)&As[kk][ma1];
        a3.f = *(const float4*)&As[kk][ma1 + 4];
        float4 b0 = *(const float4*)&Bs[kk][na0];
        float4 b1 = *(const float4*)&Bs[kk][na1];
        ull aa[8] = {a0.u[0], a0.u[1], a1.u[0], a1.u[1],
                     a2.u[0], a2.u[1], a3.u[0], a3.u[1]};
        ull bb[8] = {pack2(b0.x), pack2(b0.y), pack2(b0.z), pack2(b0.w),
                     pack2(b1.x), pack2(b1.y), pack2(b1.z), pack2(b1.w)};
#pragma unroll
        for (int mi = 0; mi < 8; mi++)
#pragma unroll
            for (int j = 0; j < 8; j++)
                acc[mi][j] = ffma2(aa[mi], bb[j], acc[mi][j]);
    }
}

template<bool AT, bool BT, bool SUMB>
__device__ __forceinline__ void gemm_core(const float* __restrict__ A, int lda,
                                          const float* __restrict__ B, int ldb,
                                          const float* __restrict__ B2,
                                          int K, int m0, int n0,
                                          int ty, int tx, ull acc[8][8])
{
    __shared__ float As[2][16][256];   // 32 KB
    __shared__ float Bs[2][16][128];   // 16 KB
    const int tid = threadIdx.x;

    // staging indices
    const int akr = tid >> 4, acol = (tid & 15) * 16;  // A direct: 16 rows x (16 thr x 16 f)
    const int bkr = tid >> 4, bcol = (tid & 15) * 8;   // B direct: 16 rows x (16 thr x 8 f)
    const int btr = tid >> 1, btc = (tid & 1) * 8;     // B transposed: 128 rows x (2 thr x 8 k)

    const float* Ap = AT ? (A + (size_t)(m0 + tid) * lda)
                         : (A + (size_t)akr * lda + m0 + acol);
    const float* Bp = BT ? (B + (size_t)(n0 + btr) * ldb + btc)
                         : (B + (size_t)bkr * ldb + n0 + bcol);
    const float* Bp2 = SUMB ? (B2 + (size_t)bkr * ldb + n0 + bcol) : Bp;

    float4 av[4], bv[2];

    // ---- prologue: stage tile 0 ----
#pragma unroll
    for (int c = 0; c < 4; c++)
        av[c] = AT ? *(const float4*)(Ap + c * 4)
                   : *(const float4*)(Ap + c * 4);
#pragma unroll
    for (int c = 0; c < 2; c++) {
        bv[c] = BT ? *(const float4*)(Bp + c * 4)
                   : *(const float4*)(Bp + c * 4);
        if (SUMB) {
            float4 b2 = *(const float4*)(Bp2 + c * 4);
            bv[c].x += b2.x; bv[c].y += b2.y; bv[c].z += b2.z; bv[c].w += b2.w;
        }
    }
    if (AT) {
#pragma unroll
        for (int c = 0; c < 4; c++) {
            As[0][c*4+0][tid] = av[c].x; As[0][c*4+1][tid] = av[c].y;
            As[0][c*4+2][tid] = av[c].z; As[0][c*4+3][tid] = av[c].w;
        }
    } else {
#pragma unroll
        for (int c = 0; c < 4; c++) *(float4*)&As[0][akr][acol + c*4] = av[c];
    }
    if (BT) {
#pragma unroll
        for (int c = 0; c < 2; c++) {
            Bs[0][btc + c*4 + 0][btr] = bv[c].x; Bs[0][btc + c*4 + 1][btr] = bv[c].y;
            Bs[0][btc + c*4 + 2][btr] = bv[c].z; Bs[0][btc + c*4 + 3][btr] = bv[c].w;
        }
    } else {
#pragma unroll
        for (int c = 0; c < 2; c++) *(float4*)&Bs[0][bkr][bcol + c*4] = bv[c];
    }
    __syncthreads();

    int buf = 0;
    for (int k0 = 16; k0 < K; k0 += 16) {
#pragma unroll
        for (int c = 0; c < 4; c++)
            av[c] = AT ? *(const float4*)(Ap + k0 + c * 4)
                       : *(const float4*)(Ap + (size_t)k0 * lda + c * 4);
#pragma unroll
        for (int c = 0; c < 2; c++) {
            bv[c] = BT ? *(const float4*)(Bp + k0 + c * 4)
                       : *(const float4*)(Bp + (size_t)k0 * ldb + c * 4);
            if (SUMB) {
                float4 b2 = *(const float4*)(Bp2 + (size_t)k0 * ldb + c * 4);
                bv[c].x += b2.x; bv[c].y += b2.y; bv[c].z += b2.z; bv[c].w += b2.w;
            }
        }

        mm256(As[buf], Bs[buf], ty, tx, acc);

        const int nb = buf ^ 1;
        if (AT) {
#pragma unroll
            for (int c = 0; c < 4; c++) {
                As[nb][c*4+0][tid] = av[c].x; As[nb][c*4+1][tid] = av[c].y;
                As[nb][c*4+2][tid] = av[c].z; As[nb][c*4+3][tid] = av[c].w;
            }
        } else {
#pragma unroll
            for (int c = 0; c < 4; c++) *(float4*)&As[nb][akr][acol + c*4] = av[c];
        }
        if (BT) {
#pragma unroll
            for (int c = 0; c < 2; c++) {
                Bs[nb][btc + c*4 + 0][btr] = bv[c].x; Bs[nb][btc + c*4 + 1][btr] = bv[c].y;
                Bs[nb][btc + c*4 + 2][btr] = bv[c].z; Bs[nb][btc + c*4 + 3][btr] = bv[c].w;
            }
        } else {
#pragma unroll
            for (int c = 0; c < 2; c++) *(float4*)&Bs[nb][bkr][bcol + c*4] = bv[c];
        }
        __syncthreads();
        buf = nb;
    }
    mm256(As[buf], Bs[buf], ty, tx, acc);
}

#define MICRO_IDX                                   \
    const int tid = threadIdx.x;                    \
    const int tx = tid & 15, ty = tid >> 4;         \
    ull acc[8][8];                                  \
    _Pragma("unroll") for (int i = 0; i < 8; i++)   \
    _Pragma("unroll") for (int j = 0; j < 8; j++) acc[i][j] = 0ull;

__device__ __forceinline__ int mrow_of(int mi, int ty) {
    return (mi < 4) ? (ty * 8 + 2 * mi) : (128 + ty * 8 + 2 * (mi - 4));
}

__device__ __forceinline__ void store_plain(float* C, int ldc, int m0, int n0,
                                            int ty, int tx, const ull acc[8][8])
{
    const int na0 = n0 + tx * 4, na1 = n0 + 64 + tx * 4;
#pragma unroll
    for (int mi = 0; mi < 8; mi++) {
        const int row = m0 + mrow_of(mi, ty);
        float2 p[8];
#pragma unroll
        for (int j = 0; j < 8; j++) p[j] = unpk2(acc[mi][j]);
        float* r0 = C + (size_t)row * ldc;
        float* r1 = C + (size_t)(row + 1) * ldc;
        *(float4*)(r0 + na0) = make_float4(p[0].x, p[1].x, p[2].x, p[3].x);
        *(float4*)(r0 + na1) = make_float4(p[4].x, p[5].x, p[6].x, p[7].x);
        *(float4*)(r1 + na0) = make_float4(p[0].y, p[1].y, p[2].y, p[3].y);
        *(float4*)(r1 + na1) = make_float4(p[4].y, p[5].y, p[6].y, p[7].y);
    }
}

// ---------------------------------------------------------------------------
// gemm1: T1_r[h,q] = sum_p Wh[p,h] * Wr[r,p,q]   M=768 N=2048 K=2048
// ---------------------------------------------------------------------------
__global__ __launch_bounds__(256, 1) void gemm1_kernel(
    const float* __restrict__ hW, const float* __restrict__ bilW)
{
    const int r  = blockIdx.z;
    const int m0 = blockIdx.y * 256;
    const int n0 = blockIdx.x * 128;
    MICRO_IDX;
    gemm_core<false, false, false>(hW, HH, bilW + (size_t)r * PP * PP, PP, nullptr,
                                   PP, m0, n0, ty, tx, acc);
    store_plain(g_T1 + (size_t)r * HH * PP, PP, m0, n0, ty, tx, acc);
}

// ---------------------------------------------------------------------------
// gemm2 (split-K=2): Mp[kh][r][h,h2] = sum_{q half} T1_r[h,q] * Wt[q,h2]
// ---------------------------------------------------------------------------
__global__ __launch_bounds__(256, 1) void gemm2_kernel(const float* __restrict__ tW)
{
    const int z  = blockIdx.z;
    const int r  = z >> 1;
    const int kh = z & 1;
    const int m0 = blockIdx.y * 256;
    const int n0 = blockIdx.x * 128;
    MICRO_IDX;
    gemm_core<true, false, false>(g_T1 + (size_t)r * HH * PP + kh * 1024, PP,
                                  tW + (size_t)kh * 1024 * HH, HH, nullptr,
                                  1024, m0, n0, ty, tx, acc);
    store_plain(g_Mp + ((size_t)kh * RR + r) * HH * HH, HH, m0, n0, ty, tx, acc);
}

// ---------------------------------------------------------------------------
// gemm3: G_r[n,h2] = sum_h F[n,h] * (Mp0_r + Mp1_r)[h,h2]   M=4096 N=768 K=768
// (split-K reduction of gemm2 folded into B staging)
// ---------------------------------------------------------------------------
__global__ __launch_bounds__(256, 1) void gemm3_kernel(const float* __restrict__ F)
{
    const int r  = blockIdx.z;
    const int m0 = blockIdx.y * 256;
    const int n0 = blockIdx.x * 128;
    MICRO_IDX;
    gemm_core<true, false, true>(F, HH,
                                 g_Mp + (size_t)r * HH * HH, HH,
                                 g_Mp + ((size_t)RR + r) * HH * HH,
                                 HH, m0, n0, ty, tx, acc);
    store_plain(g_G + (size_t)r * MROWS * HH, HH, m0, n0, ty, tx, acc);
}

// ---------------------------------------------------------------------------
// gemm4: logits[b,n,m,r] = sum_h G_r[b*256+n,h]*F[b*256+m,h] + fu + fv + s
// ---------------------------------------------------------------------------
__global__ __launch_bounds__(256, 1) void gemm4_kernel(
    const float* __restrict__ F, float* __restrict__ out)
{
    const int z = blockIdx.z;
    const int b = z / RR;
    const int r = z % RR;
    const int n0 = blockIdx.x * 128;
    MICRO_IDX;
    gemm_core<true, true, false>(g_G + ((size_t)r * MROWS + (size_t)b * NN) * HH, HH,
                                 F + (size_t)b * NN * HH, HH, nullptr,
                                 HH, 0, n0, ty, tx, acc);

    const float sv = g_s[r];
    const float* fu = g_fu + (size_t)r * MROWS + b * NN;
    const float* fv = g_fv + (size_t)r * MROWS + b * NN;

    const int na0 = n0 + tx * 4, na1 = n0 + 64 + tx * 4;
    float fvj[8];
#pragma unroll
    for (int j = 0; j < 4; j++) { fvj[j] = fv[na0 + j] + sv; fvj[j + 4] = fv[na1 + j] + sv; }

#pragma unroll
    for (int mi = 0; mi < 8; mi++) {
        const int n = mrow_of(mi, ty);
        const float fu0 = fu[n], fu1 = fu[n + 1];
        float2 p[8];
#pragma unroll
        for (int j = 0; j < 8; j++) p[j] = unpk2(acc[mi][j]);
        float* o0 = out + (((size_t)b * NN + n) * NN) * RR + r;
        float* o1 = o0 + (size_t)NN * RR;
#pragma unroll
        for (int j = 0; j < 4; j++) {
            o0[(size_t)(na0 + j) * RR] = p[j].x + fu0 + fvj[j];
            o0[(size_t)(na1 + j) * RR] = p[j + 4].x + fu0 + fvj[j + 4];
            o1[(size_t)(na0 + j) * RR] = p[j].y + fu1 + fvj[j];
            o1[(size_t)(na1 + j) * RR] = p[j + 4].y + fu1 + fvj[j + 4];
        }
    }
}

// ---------------------------------------------------------------------------
// Vector stage (deterministic partials + tree reduces) — proven
// ---------------------------------------------------------------------------
__global__ void vec_w_kernel(const float* __restrict__ bilW, const float* __restrict__ bt)
{
    const int r = blockIdx.y;
    const int warp = threadIdx.x >> 5, lane = threadIdx.x & 31;
    const int p = blockIdx.x * 8 + warp;
    const float* row = bilW + ((size_t)r * PP + p) * PP;
    float acc = 0.f;
    for (int q = lane; q < PP; q += 32) acc += row[q] * __ldg(&bt[q]);
#pragma unroll
    for (int o = 16; o; o >>= 1) acc += __shfl_down_sync(0xFFFFFFFFu, acc, o);
    if (lane == 0) g_w[r * PP + p] = acc;
}

__global__ void vec_z_part(const float* __restrict__ bilW, const float* __restrict__ bh)
{
    const int r = blockIdx.y, sp = blockIdx.z;
    const int q = blockIdx.x * 256 + threadIdx.x;
    const float* base = bilW + (size_t)r * PP * PP + (size_t)sp * 128 * PP + q;
    float acc = 0.f;
#pragma unroll 4
    for (int p = 0; p < 128; p++) acc += __ldg(&bh[sp * 128 + p]) * base[(size_t)p * PP];
    g_zp[((size_t)sp * RR + r) * PP + q] = acc;
}

__global__ void reduce_z() {
    const int o = blockIdx.x * 256 + threadIdx.x;
    float acc = 0.f;
#pragma unroll
    for (int sp = 0; sp < 16; sp++) acc += g_zp[(size_t)sp * RR * PP + o];
    g_z[o] = acc;
}

__global__ void vec_s_kernel(const float* __restrict__ bh, const float* __restrict__ bilb)
{
    const int r = blockIdx.x;
    __shared__ float red[256];
    float acc = 0.f;
    for (int p = threadIdx.x; p < PP; p += 256) acc += bh[p] * g_w[r * PP + p];
    red[threadIdx.x] = acc;
    __syncthreads();
    for (int o = 128; o; o >>= 1) {
        if (threadIdx.x < o) red[threadIdx.x] += red[threadIdx.x + o];
        __syncthreads();
    }
    if (threadIdx.x == 0) g_s[r] = red[0] + bilb[r];
}

__global__ void vec_uv_part(const float* __restrict__ hW, const float* __restrict__ tW)
{
    const int sel = blockIdx.z >> 3, sp = blockIdx.z & 7;
    const int r = blockIdx.y;
    const int h = blockIdx.x * 256 + threadIdx.x;
    const float* Wm  = sel ? tW : hW;
    const float* vin = (sel ? g_z : g_w) + (size_t)r * PP + sp * 256;
    const float* base = Wm + (size_t)sp * 256 * HH + h;
    float acc = 0.f;
#pragma unroll 4
    for (int p = 0; p < 256; p++) acc += base[(size_t)p * HH] * __ldg(&vin[p]);
    g_uvp[((size_t)(sel * 8 + sp) * RR + r) * HH + h] = acc;
}

__global__ void reduce_uv() {
    const int o = blockIdx.x * 256 + threadIdx.x;
    const int sel = o / (RR * HH);
    const int rem = o % (RR * HH);
    float acc = 0.f;
#pragma unroll
    for (int sp = 0; sp < 8; sp++) acc += g_uvp[((size_t)(sel * 8 + sp) * RR * HH) + rem];
    g_uv[o] = acc;
}

__global__ void vec_fufv_kernel(const float* __restrict__ F)
{
    const int sel = blockIdx.z;
    const int r = blockIdx.y;
    const int warp = threadIdx.x >> 5, lane = threadIdx.x & 31;
    const int n = blockIdx.x * 8 + warp;
    const float* f  = F + (size_t)n * HH;
    const float* vv = g_uv + ((size_t)sel * RR + r) * HH;
    float acc = 0.f;
    for (int h = lane; h < HH; h += 32) acc += f[h] * __ldg(&vv[h]);
#pragma unroll
    for (int o = 16; o; o >>= 1) acc += __shfl_down_sync(0xFFFFFFFFu, acc, o);
    if (lane == 0) (sel ? g_fv : g_fu)[r * MROWS + n] = acc;
}

// ---------------------------------------------------------------------------
// Launch
// ---------------------------------------------------------------------------
extern "C" void kernel_launch(void* const* d_in, const int* in_sizes, int n_in,
                              void* d_out, int out_size)
{
    const float* features = (const float*)d_in[0];
    const float* head_W   = (const float*)d_in[1];
    const float* head_b   = (const float*)d_in[2];
    const float* tail_W   = (const float*)d_in[3];
    const float* tail_b   = (const float*)d_in[4];
    const float* bil_W    = (const float*)d_in[5];
    const float* bil_b    = (const float*)d_in[6];
    float* out = (float*)d_out;

    dim3 blk(256);

    // vector/bias path
    vec_w_kernel  <<<dim3(PP / 8, RR), blk>>>(bil_W, tail_b);
    vec_z_part    <<<dim3(PP / 256, RR, 16), blk>>>(bil_W, head_b);
    reduce_z      <<<dim3(RR * PP / 256), blk>>>();
    vec_s_kernel  <<<dim3(RR), blk>>>(head_b, bil_b);
    vec_uv_part   <<<dim3(HH / 256, RR, 16), blk>>>(head_W, tail_W);
    reduce_uv     <<<dim3(2 * RR * HH / 256), blk>>>();
    vec_fufv_kernel<<<dim3(MROWS / 8, RR, 2), blk>>>(features);

    // factored GEMM chain (round-3 core, BK=16, reduceM folded into gemm3)
    gemm1_kernel  <<<dim3(PP / 128, HH / 256, RR), blk>>>(head_W, bil_W);
    gemm2_kernel  <<<dim3(HH / 128, HH / 256, RR * 2), blk>>>(tail_W);
    gemm3_kernel  <<<dim3(HH / 128, MROWS / 256, RR), blk>>>(features);
    gemm4_kernel  <<<dim3(NN / 128, NN / 256, BB * RR), blk>>>(features, out);
}

// round 13
// speedup vs baseline: 2.1707x; 1.0479x over previous
#include <cuda_runtime.h>

#define BB 16
#define NN 256
#define HH 768
#define PP 2048
#define RR 3
#define MROWS 4096

typedef unsigned long long ull;

// Scratch (__device__ globals; allocation forbidden)
__device__ float g_T1 [RR * HH * PP];       // Wh^T Wr          [3,768,2048]
__device__ float g_Mp [2 * RR * HH * HH];   // gemm2 split-K partials
__device__ float g_G  [RR * MROWS * HH];    // F @ M_r          [3,4096,768]
__device__ float g_P4 [4 * BB * RR * NN * NN]; // gemm4 split-K partials (50MB)
__device__ float g_w  [RR * PP];
__device__ float g_zp [16 * RR * PP];
__device__ float g_z  [RR * PP];
__device__ float g_uvp[16 * RR * HH];
__device__ float g_uv [2 * RR * HH];
__device__ float g_fu [RR * MROWS];
__device__ float g_fv [RR * MROWS];
__device__ float g_s  [RR];

// ---------------------------------------------------------------------------
// Packed fp32x2 helpers
// ---------------------------------------------------------------------------
__device__ __forceinline__ ull ffma2(ull a, ull b, ull c) {
    ull d;
    asm("fma.rn.f32x2 %0, %1, %2, %3;" : "=l"(d) : "l"(a), "l"(b), "l"(c));
    return d;
}
__device__ __forceinline__ ull pack2(float x) {
    ull d;
    asm("mov.b64 %0, {%1, %1};" : "=l"(d) : "f"(x));
    return d;
}
__device__ __forceinline__ float2 unpk2(ull v) {
    float2 r;
    asm("mov.b64 {%0, %1}, %2;" : "=f"(r.x), "=f"(r.y) : "l"(v));
    return r;
}
union F4U { float4 f; ull u[2]; };

// ---------------------------------------------------------------------------
// SGEMM core (round-12 proven): block tile 256(m) x 128(n), BK=16,
// 256 threads, 1 CTA/SM. Micro-tile 16x8, f32x2 packed along m.
//  AT/BT: operand stored [M,K]/[N,K] (true) vs [K,M]/[K,N] (false).
//  SUMB: B staged as elementwise sum of B and B2 (folds reduceM into gemm3).
// ---------------------------------------------------------------------------
__device__ __forceinline__ void mm256(const float (*As)[256], const float (*Bs)[128],
                                      int ty, int tx, ull acc[8][8])
{
    const int ma0 = ty * 8, ma1 = 128 + ty * 8;
    const int na0 = tx * 4, na1 = 64 + tx * 4;
#pragma unroll
    for (int kk = 0; kk < 16; kk++) {
        F4U a0, a1, a2, a3;
        a0.f = *(const float4*)&As[kk][ma0];
        a1.f = *(const float4*)&As[kk][ma0 + 4];
        a2.f = *(const float4*)&As[kk][ma1];
        a3.f = *(const float4*)&As[kk][ma1 + 4];
        float4 b0 = *(const float4*)&Bs[kk][na0];
        float4 b1 = *(const float4*)&Bs[kk][na1];
        ull aa[8] = {a0.u[0], a0.u[1], a1.u[0], a1.u[1],
                     a2.u[0], a2.u[1], a3.u[0], a3.u[1]};
        ull bb[8] = {pack2(b0.x), pack2(b0.y), pack2(b0.z), pack2(b0.w),
                     pack2(b1.x), pack2(b1.y), pack2(b1.z), pack2(b1.w)};
#pragma unroll
        for (int mi = 0; mi < 8; mi++)
#pragma unroll
            for (int j = 0; j < 8; j++)
                acc[mi][j] = ffma2(aa[mi], bb[j], acc[mi][j]);
    }
}

template<bool AT, bool BT, bool SUMB>
__device__ __forceinline__ void gemm_core(const float* __restrict__ A, int lda,
                                          const float* __restrict__ B, int ldb,
                                          const float* __restrict__ B2,
                                          int K, int m0, int n0,
                                          int ty, int tx, ull acc[8][8])
{
    __shared__ float As[2][16][256];   // 32 KB
    __shared__ float Bs[2][16][128];   // 16 KB
    const int tid = threadIdx.x;

    const int akr = tid >> 4, acol = (tid & 15) * 16;
    const int bkr = tid >> 4, bcol = (tid & 15) * 8;
    const int btr = tid >> 1, btc = (tid & 1) * 8;

    const float* Ap = AT ? (A + (size_t)(m0 + tid) * lda)
                         : (A + (size_t)akr * lda + m0 + acol);
    const float* Bp = BT ? (B + (size_t)(n0 + btr) * ldb + btc)
                         : (B + (size_t)bkr * ldb + n0 + bcol);
    const float* Bp2 = SUMB ? (B2 + (size_t)bkr * ldb + n0 + bcol) : Bp;

    float4 av[4], bv[2];

#pragma unroll
    for (int c = 0; c < 4; c++) av[c] = *(const float4*)(Ap + c * 4);
#pragma unroll
    for (int c = 0; c < 2; c++) {
        bv[c] = *(const float4*)(Bp + c * 4);
        if (SUMB) {
            float4 b2 = *(const float4*)(Bp2 + c * 4);
            bv[c].x += b2.x; bv[c].y += b2.y; bv[c].z += b2.z; bv[c].w += b2.w;
        }
    }
    if (AT) {
#pragma unroll
        for (int c = 0; c < 4; c++) {
            As[0][c*4+0][tid] = av[c].x; As[0][c*4+1][tid] = av[c].y;
            As[0][c*4+2][tid] = av[c].z; As[0][c*4+3][tid] = av[c].w;
        }
    } else {
#pragma unroll
        for (int c = 0; c < 4; c++) *(float4*)&As[0][akr][acol + c*4] = av[c];
    }
    if (BT) {
#pragma unroll
        for (int c = 0; c < 2; c++) {
            Bs[0][btc + c*4 + 0][btr] = bv[c].x; Bs[0][btc + c*4 + 1][btr] = bv[c].y;
            Bs[0][btc + c*4 + 2][btr] = bv[c].z; Bs[0][btc + c*4 + 3][btr] = bv[c].w;
        }
    } else {
#pragma unroll
        for (int c = 0; c < 2; c++) *(float4*)&Bs[0][bkr][bcol + c*4] = bv[c];
    }
    __syncthreads();

    int buf = 0;
    for (int k0 = 16; k0 < K; k0 += 16) {
#pragma unroll
        for (int c = 0; c < 4; c++)
            av[c] = AT ? *(const float4*)(Ap + k0 + c * 4)
                       : *(const float4*)(Ap + (size_t)k0 * lda + c * 4);
#pragma unroll
        for (int c = 0; c < 2; c++) {
            bv[c] = BT ? *(const float4*)(Bp + k0 + c * 4)
                       : *(const float4*)(Bp + (size_t)k0 * ldb + c * 4);
            if (SUMB) {
                float4 b2 = *(const float4*)(Bp2 + (size_t)k0 * ldb + c * 4);
                bv[c].x += b2.x; bv[c].y += b2.y; bv[c].z += b2.z; bv[c].w += b2.w;
            }
        }

        mm256(As[buf], Bs[buf], ty, tx, acc);

        const int nb = buf ^ 1;
        if (AT) {
#pragma unroll
            for (int c = 0; c < 4; c++) {
                As[nb][c*4+0][tid] = av[c].x; As[nb][c*4+1][tid] = av[c].y;
                As[nb][c*4+2][tid] = av[c].z; As[nb][c*4+3][tid] = av[c].w;
            }
        } else {
#pragma unroll
            for (int c = 0; c < 4; c++) *(float4*)&As[nb][akr][acol + c*4] = av[c];
        }
        if (BT) {
#pragma unroll
            for (int c = 0; c < 2; c++) {
                Bs[nb][btc + c*4 + 0][btr] = bv[c].x; Bs[nb][btc + c*4 + 1][btr] = bv[c].y;
                Bs[nb][btc + c*4 + 2][btr] = bv[c].z; Bs[nb][btc + c*4 + 3][btr] = bv[c].w;
            }
        } else {
#pragma unroll
            for (int c = 0; c < 2; c++) *(float4*)&Bs[nb][bkr][bcol + c*4] = bv[c];
        }
        __syncthreads();
        buf = nb;
    }
    mm256(As[buf], Bs[buf], ty, tx, acc);
}

#define MICRO_IDX                                   \
    const int tid = threadIdx.x;                    \
    const int tx = tid & 15, ty = tid >> 4;         \
    ull acc[8][8];                                  \
    _Pragma("unroll") for (int i = 0; i < 8; i++)   \
    _Pragma("unroll") for (int j = 0; j < 8; j++) acc[i][j] = 0ull;

__device__ __forceinline__ int mrow_of(int mi, int ty) {
    return (mi < 4) ? (ty * 8 + 2 * mi) : (128 + ty * 8 + 2 * (mi - 4));
}

__device__ __forceinline__ void store_plain(float* C, int ldc, int m0, int n0,
                                            int ty, int tx, const ull acc[8][8])
{
    const int na0 = n0 + tx * 4, na1 = n0 + 64 + tx * 4;
#pragma unroll
    for (int mi = 0; mi < 8; mi++) {
        const int row = m0 + mrow_of(mi, ty);
        float2 p[8];
#pragma unroll
        for (int j = 0; j < 8; j++) p[j] = unpk2(acc[mi][j]);
        float* r0 = C + (size_t)row * ldc;
        float* r1 = C + (size_t)(row + 1) * ldc;
        *(float4*)(r0 + na0) = make_float4(p[0].x, p[1].x, p[2].x, p[3].x);
        *(float4*)(r0 + na1) = make_float4(p[4].x, p[5].x, p[6].x, p[7].x);
        *(float4*)(r1 + na0) = make_float4(p[0].y, p[1].y, p[2].y, p[3].y);
        *(float4*)(r1 + na1) = make_float4(p[4].y, p[5].y, p[6].y, p[7].y);
    }
}

// ---------------------------------------------------------------------------
// gemm1: T1_r[h,q] = sum_p Wh[p,h] * Wr[r,p,q]   M=768 N=2048 K=2048
// ---------------------------------------------------------------------------
__global__ __launch_bounds__(256, 1) void gemm1_kernel(
    const float* __restrict__ hW, const float* __restrict__ bilW)
{
    const int r  = blockIdx.z;
    const int m0 = blockIdx.y * 256;
    const int n0 = blockIdx.x * 128;
    MICRO_IDX;
    gemm_core<false, false, false>(hW, HH, bilW + (size_t)r * PP * PP, PP, nullptr,
                                   PP, m0, n0, ty, tx, acc);
    store_plain(g_T1 + (size_t)r * HH * PP, PP, m0, n0, ty, tx, acc);
}

// ---------------------------------------------------------------------------
// gemm2 (split-K=2): Mp[kh][r][h,h2] = sum_{q half} T1_r[h,q] * Wt[q,h2]
// ---------------------------------------------------------------------------
__global__ __launch_bounds__(256, 1) void gemm2_kernel(const float* __restrict__ tW)
{
    const int z  = blockIdx.z;
    const int r  = z >> 1;
    const int kh = z & 1;
    const int m0 = blockIdx.y * 256;
    const int n0 = blockIdx.x * 128;
    MICRO_IDX;
    gemm_core<true, false, false>(g_T1 + (size_t)r * HH * PP + kh * 1024, PP,
                                  tW + (size_t)kh * 1024 * HH, HH, nullptr,
                                  1024, m0, n0, ty, tx, acc);
    store_plain(g_Mp + ((size_t)kh * RR + r) * HH * HH, HH, m0, n0, ty, tx, acc);
}

// ---------------------------------------------------------------------------
// gemm3: G_r[n,h2] = sum_h F[n,h] * (Mp0_r + Mp1_r)[h,h2]   M=4096 N=768 K=768
// ---------------------------------------------------------------------------
__global__ __launch_bounds__(256, 1) void gemm3_kernel(const float* __restrict__ F)
{
    const int r  = blockIdx.z;
    const int m0 = blockIdx.y * 256;
    const int n0 = blockIdx.x * 128;
    MICRO_IDX;
    gemm_core<true, false, true>(F, HH,
                                 g_Mp + (size_t)r * HH * HH, HH,
                                 g_Mp + ((size_t)RR + r) * HH * HH,
                                 HH, m0, n0, ty, tx, acc);
    store_plain(g_G + (size_t)r * MROWS * HH, HH, m0, n0, ty, tx, acc);
}

// ---------------------------------------------------------------------------
// gemm4 (split-K=4): P4[kh][z][n,m] = sum_{h in quarter} G_r[bn+n,h]*F[bm+m,h]
// grid (2, 4, 48): x = m-tile(128), y = kh, z = b*RR + r.  K=192 per block.
// ---------------------------------------------------------------------------
__global__ __launch_bounds__(256, 1) void gemm4_kernel(const float* __restrict__ F)
{
    const int z  = blockIdx.z;
    const int b  = z / RR;
    const int r  = z % RR;
    const int kh = blockIdx.y;
    const int n0 = blockIdx.x * 128;
    MICRO_IDX;
    const float* A  = g_G + ((size_t)r * MROWS + (size_t)b * NN) * HH + kh * 192;
    const float* Bm = F + (size_t)b * NN * HH + kh * 192;
    gemm_core<true, true, false>(A, HH, Bm, HH, nullptr, 192, 0, n0, ty, tx, acc);
    store_plain(g_P4 + ((size_t)kh * (BB * RR) + z) * NN * NN, NN, 0, n0, ty, tx, acc);
}

// reduce4: out[b,n,m,r] = sum_kh P4 + fu + fv + s.  48*65536 elems.
__global__ void reduce4_kernel(float* __restrict__ out)
{
    const size_t i = (size_t)blockIdx.x * 256 + threadIdx.x;  // < 48*65536
    const int z    = (int)(i >> 16);
    const int rem  = (int)(i & 65535);
    const int nrow = rem >> 8, mcol = rem & 255;
    const int b = z / RR, r = z % RR;
    const size_t plane = (size_t)(BB * RR) * NN * NN;
    float a = g_P4[i] + g_P4[plane + i] + g_P4[2 * plane + i] + g_P4[3 * plane + i];
    a += g_fu[r * MROWS + b * NN + nrow] + g_fv[r * MROWS + b * NN + mcol] + g_s[r];
    out[(((size_t)b * NN + nrow) * NN + mcol) * RR + r] = a;
}

// ---------------------------------------------------------------------------
// Vector stage (merged launches)
// ---------------------------------------------------------------------------
// blocks [0,768): w[r,p] row-dots; blocks [768,1152): zp partials.
__global__ void vec_wz_kernel(const float* __restrict__ bilW,
                              const float* __restrict__ bt,
                              const float* __restrict__ bh)
{
    int bid = blockIdx.x;
    if (bid < 768) {
        const int r = bid / 256, px = bid % 256;
        const int warp = threadIdx.x >> 5, lane = threadIdx.x & 31;
        const int p = px * 8 + warp;
        const float* row = bilW + ((size_t)r * PP + p) * PP;
        float a = 0.f;
        for (int q = lane; q < PP; q += 32) a += row[q] * __ldg(&bt[q]);
#pragma unroll
        for (int o = 16; o; o >>= 1) a += __shfl_down_sync(0xFFFFFFFFu, a, o);
        if (lane == 0) g_w[r * PP + p] = a;
    } else {
        bid -= 768;
        const int x = bid & 7, r = (bid >> 3) % 3, sp = bid / 24;
        const int q = x * 256 + threadIdx.x;
        const float* base = bilW + (size_t)r * PP * PP + (size_t)sp * 128 * PP + q;
        float a = 0.f;
#pragma unroll 4
        for (int p = 0; p < 128; p++) a += __ldg(&bh[sp * 128 + p]) * base[(size_t)p * PP];
        g_zp[((size_t)sp * RR + r) * PP + q] = a;
    }
}

// blocks [0,24): reduce z; blocks [24,27): s[r].
__global__ void reduce_z_s_kernel(const float* __restrict__ bh,
                                  const float* __restrict__ bilb)
{
    if (blockIdx.x < 24) {
        const int o = blockIdx.x * 256 + threadIdx.x;
        float a = 0.f;
#pragma unroll
        for (int sp = 0; sp < 16; sp++) a += g_zp[(size_t)sp * RR * PP + o];
        g_z[o] = a;
    } else {
        const int r = blockIdx.x - 24;
        __shared__ float red[256];
        float a = 0.f;
        for (int p = threadIdx.x; p < PP; p += 256) a += bh[p] * g_w[r * PP + p];
        red[threadIdx.x] = a;
        __syncthreads();
        for (int o = 128; o; o >>= 1) {
            if (threadIdx.x < o) red[threadIdx.x] += red[threadIdx.x + o];
            __syncthreads();
        }
        if (threadIdx.x == 0) g_s[r] = red[0] + bilb[r];
    }
}

__global__ void vec_uv_part(const float* __restrict__ hW, const float* __restrict__ tW)
{
    const int sel = blockIdx.z >> 3, sp = blockIdx.z & 7;
    const int r = blockIdx.y;
    const int h = blockIdx.x * 256 + threadIdx.x;
    const float* Wm  = sel ? tW : hW;
    const float* vin = (sel ? g_z : g_w) + (size_t)r * PP + sp * 256;
    const float* base = Wm + (size_t)sp * 256 * HH + h;
    float a = 0.f;
#pragma unroll 4
    for (int p = 0; p < 256; p++) a += base[(size_t)p * HH] * __ldg(&vin[p]);
    g_uvp[((size_t)(sel * 8 + sp) * RR + r) * HH + h] = a;
}

__global__ void reduce_uv() {
    const int o = blockIdx.x * 256 + threadIdx.x;
    const int sel = o / (RR * HH);
    const int rem = o % (RR * HH);
    float a = 0.f;
#pragma unroll
    for (int sp = 0; sp < 8; sp++) a += g_uvp[((size_t)(sel * 8 + sp) * RR * HH) + rem];
    g_uv[o] = a;
}

__global__ void vec_fufv_kernel(const float* __restrict__ F)
{
    const int sel = blockIdx.z;
    const int r = blockIdx.y;
    const int warp = threadIdx.x >> 5, lane = threadIdx.x & 31;
    const int n = blockIdx.x * 8 + warp;
    const float* f  = F + (size_t)n * HH;
    const float* vv = g_uv + ((size_t)sel * RR + r) * HH;
    float a = 0.f;
    for (int h = lane; h < HH; h += 32) a += f[h] * __ldg(&vv[h]);
#pragma unroll
    for (int o = 16; o; o >>= 1) a += __shfl_down_sync(0xFFFFFFFFu, a, o);
    if (lane == 0) (sel ? g_fv : g_fu)[r * MROWS + n] = a;
}

// ---------------------------------------------------------------------------
// Launch
// ---------------------------------------------------------------------------
extern "C" void kernel_launch(void* const* d_in, const int* in_sizes, int n_in,
                              void* d_out, int out_size)
{
    const float* features = (const float*)d_in[0];
    const float* head_W   = (const float*)d_in[1];
    const float* head_b   = (const float*)d_in[2];
    const float* tail_W   = (const float*)d_in[3];
    const float* tail_b   = (const float*)d_in[4];
    const float* bil_W    = (const float*)d_in[5];
    const float* bil_b    = (const float*)d_in[6];
    float* out = (float*)d_out;

    dim3 blk(256);

    // vector/bias path (merged launches)
    vec_wz_kernel   <<<dim3(1152), blk>>>(bil_W, tail_b, head_b);
    reduce_z_s_kernel<<<dim3(27), blk>>>(head_b, bil_b);
    vec_uv_part     <<<dim3(HH / 256, RR, 16), blk>>>(head_W, tail_W);
    reduce_uv       <<<dim3(2 * RR * HH / 256), blk>>>();
    vec_fufv_kernel <<<dim3(MROWS / 8, RR, 2), blk>>>(features);

    // factored GEMM chain
    gemm1_kernel  <<<dim3(PP / 128, HH / 256, RR), blk>>>(head_W, bil_W);
    gemm2_kernel  <<<dim3(HH / 128, HH / 256, RR * 2), blk>>>(tail_W);
    gemm3_kernel  <<<dim3(HH / 128, MROWS / 256, RR), blk>>>(features);
    gemm4_kernel  <<<dim3(NN / 128, 4, BB * RR), blk>>>(features);
    reduce4_kernel<<<dim3(BB * RR * NN * NN / 256), blk>>>(out);
}